// round 1
// baseline (speedup 1.0000x reference)
#include <cuda_runtime.h>
#include <math.h>

// Problem constants
#define BB 2
#define SS 2048
#define DD 1024
#define HH 16
#define HD 64
#define D3 (3 * DD)

// Scratch (no allocation allowed -> __device__ globals)
__device__ float g_qkv[BB * SS * D3];    // [B,S,3D]: q | k | v column blocks
__device__ float g_attn[BB * SS * DD];   // [B,S,D] attention output (head-interleaved)

// ---------------------------------------------------------------------------
// SGEMM: C[M,N] = A[M,K] @ W[K,N] + bias[N]
// BM=BN=128, BK=8, 256 threads, 8x8 per-thread microtile.
// Requires M%128==0, N%128==0, K%8==0 (true for all three calls).
// ---------------------------------------------------------------------------
#define GBM 128
#define GBN 128
#define GBK 8
#define GTM 8
#define GTN 8

__global__ void __launch_bounds__(256)
sgemm_bias_kernel(const float* __restrict__ A, const float* __restrict__ W,
                  const float* __restrict__ bias, float* __restrict__ C,
                  int M, int N, int K)
{
    __shared__ float As[GBK][GBM];
    __shared__ float Bs[GBK][GBN];

    const int tid = threadIdx.x;
    const int tx = (tid % (GBN / GTN)) * GTN;   // 0..120 step 8
    const int ty = (tid / (GBN / GTN)) * GTM;   // 0..120 step 8

    const float* Ab = A + (size_t)blockIdx.y * GBM * K;
    const float* Wb = W + (size_t)blockIdx.x * GBN;

    float acc[GTM][GTN];
    #pragma unroll
    for (int i = 0; i < GTM; i++)
        #pragma unroll
        for (int j = 0; j < GTN; j++) acc[i][j] = 0.f;

    const int arow = tid / 2;            // 0..127
    const int acol = (tid % 2) * 4;      // 0 or 4
    const int brow = tid / 32;           // 0..7
    const int bcol = (tid % 32) * 4;     // 0..124

    for (int k0 = 0; k0 < K; k0 += GBK) {
        // load A tile (transposed into As)
        float4 av = *(const float4*)(Ab + (size_t)arow * K + k0 + acol);
        As[acol + 0][arow] = av.x;
        As[acol + 1][arow] = av.y;
        As[acol + 2][arow] = av.z;
        As[acol + 3][arow] = av.w;
        // load W tile
        *(float4*)&Bs[brow][bcol] =
            *(const float4*)(Wb + (size_t)(k0 + brow) * N + bcol);
        __syncthreads();

        #pragma unroll
        for (int k = 0; k < GBK; k++) {
            float ar[GTM], br[GTN];
            #pragma unroll
            for (int i = 0; i < GTM; i += 4)
                *(float4*)&ar[i] = *(const float4*)&As[k][ty + i];
            #pragma unroll
            for (int j = 0; j < GTN; j += 4)
                *(float4*)&br[j] = *(const float4*)&Bs[k][tx + j];
            #pragma unroll
            for (int i = 0; i < GTM; i++)
                #pragma unroll
                for (int j = 0; j < GTN; j++)
                    acc[i][j] += ar[i] * br[j];
        }
        __syncthreads();
    }

    const int cbase = blockIdx.x * GBN + tx;
    #pragma unroll
    for (int i = 0; i < GTM; i++) {
        float* crow = C + (size_t)(blockIdx.y * GBM + ty + i) * N + cbase;
        #pragma unroll
        for (int j = 0; j < GTN; j += 4) {
            float4 bv = *(const float4*)(bias + cbase + j);
            float4 o;
            o.x = acc[i][j + 0] + bv.x;
            o.y = acc[i][j + 1] + bv.y;
            o.z = acc[i][j + 2] + bv.z;
            o.w = acc[i][j + 3] + bv.w;
            *(float4*)(crow + j) = o;
        }
    }
}

// ---------------------------------------------------------------------------
// Flash attention: one thread per query row; 128 query rows per block.
// K/V tiles of 64 rows staged in smem (broadcast reads -> conflict-free).
// Online softmax with 16-key chunks.
// grid: (S/128, B*H), block: 128 threads.
// ---------------------------------------------------------------------------
#define AT_BM 128
#define AT_KT 64
#define AT_CH 16

__global__ void __launch_bounds__(128)
attn_kernel(const float* __restrict__ qkv, float* __restrict__ attn)
{
    __shared__ float Ksm[AT_KT][HD];
    __shared__ float Vsm[AT_KT][HD];

    const int bh = blockIdx.y;
    const int b  = bh / HH;
    const int h  = bh % HH;
    const int qrow = blockIdx.x * AT_BM + threadIdx.x;

    const float* base = qkv + (size_t)b * SS * D3;

    // load this thread's query row into registers
    float q[HD];
    const float* qptr = base + (size_t)qrow * D3 + h * HD;
    #pragma unroll
    for (int d = 0; d < HD; d += 4) {
        float4 v = *(const float4*)(qptr + d);
        q[d + 0] = v.x; q[d + 1] = v.y; q[d + 2] = v.z; q[d + 3] = v.w;
    }

    float o[HD];
    #pragma unroll
    for (int d = 0; d < HD; d++) o[d] = 0.f;
    float m = -INFINITY, l = 0.f;

    const float scale = 0.125f;  // 1/sqrt(64)

    for (int kt = 0; kt < SS; kt += AT_KT) {
        __syncthreads();
        // stage K and V tiles: 64 rows x 64 floats each, via float4
        for (int i = threadIdx.x; i < AT_KT * (HD / 4); i += AT_BM) {
            int r = i / (HD / 4);
            int c = (i % (HD / 4)) * 4;
            const float* krow = base + (size_t)(kt + r) * D3 + DD + h * HD + c;
            const float* vrow = base + (size_t)(kt + r) * D3 + 2 * DD + h * HD + c;
            *(float4*)&Ksm[r][c] = *(const float4*)krow;
            *(float4*)&Vsm[r][c] = *(const float4*)vrow;
        }
        __syncthreads();

        #pragma unroll
        for (int j0 = 0; j0 < AT_KT; j0 += AT_CH) {
            float s[AT_CH];
            #pragma unroll
            for (int j = 0; j < AT_CH; j++) {
                float acc = 0.f;
                #pragma unroll
                for (int d4 = 0; d4 < HD / 4; d4++) {
                    float4 kv = *(const float4*)&Ksm[j0 + j][d4 * 4];
                    acc += q[d4 * 4 + 0] * kv.x;
                    acc += q[d4 * 4 + 1] * kv.y;
                    acc += q[d4 * 4 + 2] * kv.z;
                    acc += q[d4 * 4 + 3] * kv.w;
                }
                s[j] = acc * scale;
            }
            // chunk max
            float mc = s[0];
            #pragma unroll
            for (int j = 1; j < AT_CH; j++) mc = fmaxf(mc, s[j]);
            float mnew = fmaxf(m, mc);
            float corr = __expf(m - mnew);   // exp(-inf)=0 on first chunk
            l *= corr;
            #pragma unroll
            for (int d = 0; d < HD; d++) o[d] *= corr;
            #pragma unroll
            for (int j = 0; j < AT_CH; j++) {
                float p = __expf(s[j] - mnew);
                l += p;
                #pragma unroll
                for (int d4 = 0; d4 < HD / 4; d4++) {
                    float4 vv = *(const float4*)&Vsm[j0 + j][d4 * 4];
                    o[d4 * 4 + 0] += p * vv.x;
                    o[d4 * 4 + 1] += p * vv.y;
                    o[d4 * 4 + 2] += p * vv.z;
                    o[d4 * 4 + 3] += p * vv.w;
                }
            }
            m = mnew;
        }
    }

    const float inv = 1.f / l;
    float* outp = attn + (size_t)b * SS * DD + (size_t)qrow * DD + h * HD;
    #pragma unroll
    for (int d = 0; d < HD; d += 4) {
        float4 v;
        v.x = o[d + 0] * inv;
        v.y = o[d + 1] * inv;
        v.z = o[d + 2] * inv;
        v.w = o[d + 3] * inv;
        *(float4*)(outp + d) = v;
    }
}

// ---------------------------------------------------------------------------
// Launch
// ---------------------------------------------------------------------------
extern "C" void kernel_launch(void* const* d_in, const int* in_sizes, int n_in,
                              void* d_out, int out_size)
{
    const float* x     = (const float*)d_in[0];   // [B,S,D]
    const float* W_qkv = (const float*)d_in[1];   // [D,3D]
    const float* b_qkv = (const float*)d_in[2];   // [3D]
    const float* W_out = (const float*)d_in[3];   // [D,D]
    const float* b_out = (const float*)d_in[4];   // [D]
    float* out = (float*)d_out;                   // [B,S,D]

    float* qkv  = nullptr;
    float* attn = nullptr;
    cudaGetSymbolAddress((void**)&qkv,  g_qkv);
    cudaGetSymbolAddress((void**)&attn, g_attn);

    const int M = BB * SS;  // 4096

    // 1) fused QKV projection: [4096,1024] @ [1024,3072] + bias
    {
        dim3 grid(D3 / GBN, M / GBM);
        sgemm_bias_kernel<<<grid, 256>>>(x, W_qkv, b_qkv, qkv, M, D3, DD);
    }

    // 2) attention (flash-style, per head)
    {
        dim3 grid(SS / AT_BM, BB * HH);
        attn_kernel<<<grid, 128>>>(qkv, attn);
    }

    // 3) output projection: [4096,1024] @ [1024,1024] + bias -> d_out
    {
        dim3 grid(DD / GBN, M / GBM);
        sgemm_bias_kernel<<<grid, 256>>>(attn, W_out, b_out, out, M, DD, DD);
    }
}

// round 2
// speedup vs baseline: 4.1725x; 4.1725x over previous
#include <cuda_runtime.h>
#include <math.h>

// Problem constants
#define BB 2
#define SS 2048
#define DD 1024
#define HH 16
#define HD 64
#define D3 (3 * DD)

// Scratch (no allocation allowed -> __device__ globals)
__device__ float g_qkv[BB * SS * D3];    // [B,S,3D]: q | k | v
__device__ float g_attn[BB * SS * DD];   // [B,S,D] attention output

// ---------------------------------------------------------------------------
// Helpers
// ---------------------------------------------------------------------------
// Round fp32 to tf32 (round-to-nearest on the 19 kept bits) via bit trick.
// mma.tf32 ignores the low 13 mantissa bits, so +0x1000 implements RN.
__device__ __forceinline__ float rtf(float x) {
    return __int_as_float(__float_as_int(x) + 0x1000);
}
__device__ __forceinline__ unsigned rtu(float x) {
    return (unsigned)(__float_as_int(x) + 0x1000);
}

// Fast exp2 for x <= 0 (clamped at -126): all FFMA/ALU, no MUFU, no F2I.
// Magic constant 12582912.f = 1.5*2^23 (low 9 bits of its int repr are 0,
// so (i<<23) directly yields the exponent offset).
__device__ __forceinline__ float exp2_fast(float x) {
    x = fmaxf(x, -126.0f);
    float z = x + 12582912.0f;
    int   i = __float_as_int(z);
    float f = x - (z - 12582912.0f);          // f in [-0.5, 0.5]
    float p = 1.33335581e-3f;
    p = fmaf(p, f, 9.61812910e-3f);
    p = fmaf(p, f, 5.55041087e-2f);
    p = fmaf(p, f, 2.40226507e-1f);
    p = fmaf(p, f, 6.93147181e-1f);
    p = fmaf(p, f, 1.0f);
    return __int_as_float(__float_as_int(p) + (i << 23));
}

#define MMA_TF32(d, a, b)                                                     \
    asm volatile(                                                             \
        "mma.sync.aligned.m16n8k8.row.col.f32.tf32.tf32.f32 "                 \
        "{%0,%1,%2,%3}, {%4,%5,%6,%7}, {%8,%9}, {%0,%1,%2,%3};"               \
        : "+f"((d)[0]), "+f"((d)[1]), "+f"((d)[2]), "+f"((d)[3])              \
        : "r"((a)[0]), "r"((a)[1]), "r"((a)[2]), "r"((a)[3]),                 \
          "r"((b)[0]), "r"((b)[1]))

// ---------------------------------------------------------------------------
// TF32 tensor-core GEMM: C[M,N] = A[M,K] @ W[K,N] + bias
// Block 128x128x16, 256 threads (8 warps, 4x2), warp tile 32x64.
// Smem pads chosen so every fragment load is bank-conflict-free:
//   As stride 20 (lane bank = (20g+t)%32 distinct), Bs stride 136 ((8t+g)).
// ---------------------------------------------------------------------------
#define ASTR 20
#define BSTR 136

__global__ void __launch_bounds__(256)
tgemm_bias(const float* __restrict__ A, const float* __restrict__ W,
           const float* __restrict__ bias, float* __restrict__ C,
           int M, int N, int K)
{
    __shared__ float As[2][128 * ASTR];
    __shared__ float Bs[2][16 * BSTR];

    const int tid  = threadIdx.x;
    const int lane = tid & 31, wid = tid >> 5;
    const int g = lane >> 2, t = lane & 3;
    const int wm = wid & 3, wn = wid >> 2;          // 4 m-warps x 2 n-warps
    const int bm0 = blockIdx.y * 128, bn0 = blockIdx.x * 128;

    const int arow = tid >> 1, acol = (tid & 1) * 8;
    const int brow = tid >> 4, bcol = (tid & 15) * 8;

    float c[2][8][4];
    #pragma unroll
    for (int mt = 0; mt < 2; mt++)
        #pragma unroll
        for (int nt = 0; nt < 8; nt++)
            #pragma unroll
            for (int r = 0; r < 4; r++) c[mt][nt][r] = 0.f;

    const float* Ag = A + (size_t)(bm0 + arow) * K + acol;
    const float* Wg = W + (size_t)brow * N + bn0 + bcol;

    float4 ra0, ra1, rb0, rb1;

#define LDG_TILE(k0)                                                          \
    do {                                                                      \
        const float* ap = Ag + (k0);                                          \
        ra0 = *(const float4*)ap; ra1 = *(const float4*)(ap + 4);             \
        const float* wp = Wg + (size_t)(k0) * N;                              \
        rb0 = *(const float4*)wp; rb1 = *(const float4*)(wp + 4);             \
    } while (0)

#define STS_TILE(bf)                                                          \
    do {                                                                      \
        float* ad = &As[bf][arow * ASTR + acol];                              \
        float4 av0 = make_float4(rtf(ra0.x), rtf(ra0.y), rtf(ra0.z), rtf(ra0.w)); \
        float4 av1 = make_float4(rtf(ra1.x), rtf(ra1.y), rtf(ra1.z), rtf(ra1.w)); \
        *(float4*)ad = av0; *(float4*)(ad + 4) = av1;                         \
        float* bd = &Bs[bf][brow * BSTR + bcol];                              \
        float4 bv0 = make_float4(rtf(rb0.x), rtf(rb0.y), rtf(rb0.z), rtf(rb0.w)); \
        float4 bv1 = make_float4(rtf(rb1.x), rtf(rb1.y), rtf(rb1.z), rtf(rb1.w)); \
        *(float4*)bd = bv0; *(float4*)(bd + 4) = bv1;                         \
    } while (0)

    LDG_TILE(0);
    STS_TILE(0);
    __syncthreads();

    const int nIter = K / 16;
    int buf = 0;
    for (int it = 0; it < nIter; ++it) {
        const bool hasNext = (it + 1 < nIter);
        if (hasNext) LDG_TILE((it + 1) * 16);

        const float* As_ = As[buf];
        const float* Bs_ = Bs[buf];
        #pragma unroll
        for (int ks = 0; ks < 2; ks++) {
            const int kk = ks * 8;
            unsigned a[2][4], bfr[8][2];
            #pragma unroll
            for (int mt = 0; mt < 2; mt++) {
                const int r0 = wm * 32 + mt * 16 + g;
                a[mt][0] = __float_as_uint(As_[r0 * ASTR + kk + t]);
                a[mt][1] = __float_as_uint(As_[(r0 + 8) * ASTR + kk + t]);
                a[mt][2] = __float_as_uint(As_[r0 * ASTR + kk + t + 4]);
                a[mt][3] = __float_as_uint(As_[(r0 + 8) * ASTR + kk + t + 4]);
            }
            #pragma unroll
            for (int nt = 0; nt < 8; nt++) {
                const int cb = wn * 64 + nt * 8 + g;
                bfr[nt][0] = __float_as_uint(Bs_[(kk + t) * BSTR + cb]);
                bfr[nt][1] = __float_as_uint(Bs_[(kk + t + 4) * BSTR + cb]);
            }
            #pragma unroll
            for (int mt = 0; mt < 2; mt++)
                #pragma unroll
                for (int nt = 0; nt < 8; nt++)
                    MMA_TF32(c[mt][nt], a[mt], bfr[nt]);
        }
        if (hasNext) {
            STS_TILE(buf ^ 1);
            __syncthreads();
            buf ^= 1;
        }
    }

    // epilogue: bias + store
    #pragma unroll
    for (int mt = 0; mt < 2; mt++) {
        const int row = bm0 + wm * 32 + mt * 16 + g;
        #pragma unroll
        for (int nt = 0; nt < 8; nt++) {
            const int col = bn0 + wn * 64 + nt * 8 + 2 * t;
            float2 bv = *(const float2*)(bias + col);
            float2 o0 = make_float2(c[mt][nt][0] + bv.x, c[mt][nt][1] + bv.y);
            float2 o1 = make_float2(c[mt][nt][2] + bv.x, c[mt][nt][3] + bv.y);
            *(float2*)(C + (size_t)row * N + col) = o0;
            *(float2*)(C + (size_t)(row + 8) * N + col) = o1;
        }
    }
#undef LDG_TILE
#undef STS_TILE
}

// ---------------------------------------------------------------------------
// TF32 tensor-core flash attention.
// grid (S/64, B*H), 128 threads (4 warps). Each warp owns 16 query rows.
// Q fragments live in registers for the whole kernel (scale+log2e folded in).
// K tile [64][68] and V tile [64][72] in smem (conflict-free frag strides).
// S-acc -> P a-fragments via register shuffles (no smem round trip).
// ---------------------------------------------------------------------------
#define KSTR 68
#define VSTR 72
#define QSCALE 0.18033688f   // (1/sqrt(64)) * log2(e)

__global__ void __launch_bounds__(128)
attn_tc_kernel(const float* __restrict__ qkv, float* __restrict__ attn)
{
    __shared__ float Ks[64 * KSTR];
    __shared__ float Vs[64 * VSTR];

    const int tid  = threadIdx.x;
    const int lane = tid & 31, wid = tid >> 5;
    const int g = lane >> 2, t = lane & 3;
    const int bh = blockIdx.y, b = bh >> 4, h = bh & 15;
    const int q0 = blockIdx.x * 64;
    const int rb = wid * 16;                       // warp's query-row base

    const float* base = qkv + (size_t)b * SS * D3;

    // Q fragments (held in registers across the whole key loop)
    unsigned qa[8][4];
    {
        const float* qp = base + (size_t)q0 * D3 + h * HD;
        #pragma unroll
        for (int kc = 0; kc < 8; kc++) {
            const int cidx = kc * 8 + t;
            qa[kc][0] = rtu(qp[(size_t)(rb + g) * D3 + cidx] * QSCALE);
            qa[kc][1] = rtu(qp[(size_t)(rb + g + 8) * D3 + cidx] * QSCALE);
            qa[kc][2] = rtu(qp[(size_t)(rb + g) * D3 + cidx + 4] * QSCALE);
            qa[kc][3] = rtu(qp[(size_t)(rb + g + 8) * D3 + cidx + 4] * QSCALE);
        }
    }

    float o[8][4];
    #pragma unroll
    for (int nt = 0; nt < 8; nt++)
        #pragma unroll
        for (int r = 0; r < 4; r++) o[nt][r] = 0.f;

    float m0 = -1e30f, m1 = -1e30f, l0 = 0.f, l1 = 0.f;
    const int srcA = (lane & ~3) | (t >> 1);   // lane holding P[g][t] (c0/c1)
    const int srcB = srcA + 2;                 // lane holding P[g][t+4]

    for (int kt = 0; kt < SS; kt += 64) {
        __syncthreads();
        // stage K and V tiles (rounded to tf32)
        for (int j = tid; j < 1024; j += 128) {
            const int row = j >> 4, c4 = (j & 15) << 2;
            const float* kp = base + (size_t)(kt + row) * D3 + DD + h * HD + c4;
            float4 kv = *(const float4*)kp;
            float4 vv = *(const float4*)(kp + DD);
            *(float4*)&Ks[row * KSTR + c4] =
                make_float4(rtf(kv.x), rtf(kv.y), rtf(kv.z), rtf(kv.w));
            *(float4*)&Vs[row * VSTR + c4] =
                make_float4(rtf(vv.x), rtf(vv.y), rtf(vv.z), rtf(vv.w));
        }
        __syncthreads();

        // S = Q K^T  (16 q-rows x 64 keys per warp), scores pre-scaled
        float s[8][4];
        #pragma unroll
        for (int nt = 0; nt < 8; nt++)
            #pragma unroll
            for (int r = 0; r < 4; r++) s[nt][r] = 0.f;

        #pragma unroll
        for (int kc = 0; kc < 8; kc++) {
            #pragma unroll
            for (int nt = 0; nt < 8; nt++) {
                unsigned bfr[2];
                bfr[0] = __float_as_uint(Ks[(nt * 8 + g) * KSTR + kc * 8 + t]);
                bfr[1] = __float_as_uint(Ks[(nt * 8 + g) * KSTR + kc * 8 + t + 4]);
                MMA_TF32(s[nt], qa[kc], bfr);
            }
        }

        // online softmax (base-2 domain; rows rb+g and rb+g+8)
        float cm0 = s[0][0], cm1 = s[0][2];
        #pragma unroll
        for (int nt = 0; nt < 8; nt++) {
            cm0 = fmaxf(cm0, fmaxf(s[nt][0], s[nt][1]));
            cm1 = fmaxf(cm1, fmaxf(s[nt][2], s[nt][3]));
        }
        cm0 = fmaxf(cm0, __shfl_xor_sync(0xffffffffu, cm0, 1));
        cm0 = fmaxf(cm0, __shfl_xor_sync(0xffffffffu, cm0, 2));
        cm1 = fmaxf(cm1, __shfl_xor_sync(0xffffffffu, cm1, 1));
        cm1 = fmaxf(cm1, __shfl_xor_sync(0xffffffffu, cm1, 2));

        const float mn0 = fmaxf(m0, cm0);
        const float mn1 = fmaxf(m1, cm1);
        const float corr0 = exp2_fast(m0 - mn0);
        const float corr1 = exp2_fast(m1 - mn1);
        m0 = mn0; m1 = mn1;

        float rs0 = 0.f, rs1 = 0.f;
        #pragma unroll
        for (int nt = 0; nt < 8; nt++) {
            float p;
            p = rtf(exp2_fast(s[nt][0] - mn0)); s[nt][0] = p; rs0 += p;
            p = rtf(exp2_fast(s[nt][1] - mn0)); s[nt][1] = p; rs0 += p;
            p = rtf(exp2_fast(s[nt][2] - mn1)); s[nt][2] = p; rs1 += p;
            p = rtf(exp2_fast(s[nt][3] - mn1)); s[nt][3] = p; rs1 += p;
            o[nt][0] *= corr0; o[nt][1] *= corr0;
            o[nt][2] *= corr1; o[nt][3] *= corr1;
        }
        rs0 += __shfl_xor_sync(0xffffffffu, rs0, 1);
        rs0 += __shfl_xor_sync(0xffffffffu, rs0, 2);
        rs1 += __shfl_xor_sync(0xffffffffu, rs1, 1);
        rs1 += __shfl_xor_sync(0xffffffffu, rs1, 2);
        l0 = l0 * corr0 + rs0;
        l1 = l1 * corr1 + rs1;

        // O += P V : rearrange P acc-layout -> A-fragments via shuffles
        #pragma unroll
        for (int kc = 0; kc < 8; kc++) {
            unsigned pa[4];
            {
                float v0 = __shfl_sync(0xffffffffu, s[kc][0], srcA);
                float v1 = __shfl_sync(0xffffffffu, s[kc][1], srcA);
                pa[0] = __float_as_uint((t & 1) ? v1 : v0);
                float v2 = __shfl_sync(0xffffffffu, s[kc][2], srcA);
                float v3 = __shfl_sync(0xffffffffu, s[kc][3], srcA);
                pa[1] = __float_as_uint((t & 1) ? v3 : v2);
                v0 = __shfl_sync(0xffffffffu, s[kc][0], srcB);
                v1 = __shfl_sync(0xffffffffu, s[kc][1], srcB);
                pa[2] = __float_as_uint((t & 1) ? v1 : v0);
                v2 = __shfl_sync(0xffffffffu, s[kc][2], srcB);
                v3 = __shfl_sync(0xffffffffu, s[kc][3], srcB);
                pa[3] = __float_as_uint((t & 1) ? v3 : v2);
            }
            #pragma unroll
            for (int nt = 0; nt < 8; nt++) {
                unsigned bfr[2];
                bfr[0] = __float_as_uint(Vs[(kc * 8 + t) * VSTR + nt * 8 + g]);
                bfr[1] = __float_as_uint(Vs[(kc * 8 + t + 4) * VSTR + nt * 8 + g]);
                MMA_TF32(o[nt], pa, bfr);
            }
        }
    }

    // normalize + write (head-interleaved [B,S,D] so transpose is free)
    const float inv0 = 1.f / l0;
    const float inv1 = 1.f / l1;
    float* op = attn + (size_t)b * SS * DD + (size_t)(q0 + rb + g) * DD + h * HD;
    #pragma unroll
    for (int nt = 0; nt < 8; nt++) {
        const int col = nt * 8 + 2 * t;
        *(float2*)(op + col) =
            make_float2(o[nt][0] * inv0, o[nt][1] * inv0);
        *(float2*)(op + (size_t)8 * DD + col) =
            make_float2(o[nt][2] * inv1, o[nt][3] * inv1);
    }
}

// ---------------------------------------------------------------------------
// Launch
// ---------------------------------------------------------------------------
extern "C" void kernel_launch(void* const* d_in, const int* in_sizes, int n_in,
                              void* d_out, int out_size)
{
    const float* x     = (const float*)d_in[0];   // [B,S,D]
    const float* W_qkv = (const float*)d_in[1];   // [D,3D]
    const float* b_qkv = (const float*)d_in[2];   // [3D]
    const float* W_out = (const float*)d_in[3];   // [D,D]
    const float* b_out = (const float*)d_in[4];   // [D]
    float* out = (float*)d_out;                   // [B,S,D]

    float* qkv  = nullptr;
    float* attn = nullptr;
    cudaGetSymbolAddress((void**)&qkv,  g_qkv);
    cudaGetSymbolAddress((void**)&attn, g_attn);

    const int M = BB * SS;  // 4096

    // 1) fused QKV projection: [4096,1024] @ [1024,3072] + bias
    {
        dim3 grid(D3 / 128, M / 128);
        tgemm_bias<<<grid, 256>>>(x, W_qkv, b_qkv, qkv, M, D3, DD);
    }
    // 2) flash attention (tf32 tensor cores)
    {
        dim3 grid(SS / 64, BB * HH);
        attn_tc_kernel<<<grid, 128>>>(qkv, attn);
    }
    // 3) output projection: [4096,1024] @ [1024,1024] + bias -> d_out
    {
        dim3 grid(DD / 128, M / 128);
        tgemm_bias<<<grid, 256>>>(attn, W_out, b_out, out, M, DD, DD);
    }
}

// round 4
// speedup vs baseline: 4.6605x; 1.1170x over previous
#include <cuda_runtime.h>
#include <math.h>
#include <stdint.h>

// Problem constants
#define BB 2
#define SS 2048
#define DD 1024
#define HH 16
#define HD 64
#define D3 (3 * DD)
#define MM (BB * SS)   // 4096

// ---------------------------------------------------------------------------
// Global scratch (no allocation allowed)
// ---------------------------------------------------------------------------
__device__ float g_qkv[MM * D3];     // [B,S,3D] fp32
__device__ float g_attn[MM * DD];    // [B,S,D] fp32
__device__ float g_xr[MM * DD];      // x, tf32-rounded
__device__ float g_ar[MM * DD];      // attn, tf32-rounded
__device__ float g_wqt[D3 * DD];     // W_qkv^T [N=3072][K=1024], tf32-rounded
__device__ float g_wot[DD * DD];     // W_out^T [N=1024][K=1024], tf32-rounded

// ---------------------------------------------------------------------------
// Helpers
// ---------------------------------------------------------------------------
// Round fp32 to tf32 (RN on kept 19 bits; mma ignores low 13 bits).
__device__ __forceinline__ float rtf(float x) {
    return __int_as_float(__float_as_int(x) + 0x1000);
}
__device__ __forceinline__ unsigned rtu(float x) {
    return (unsigned)(__float_as_int(x) + 0x1000);
}
// Fast exp2 (x <= 0, clamped at -126): FFMA-only, no MUFU.
__device__ __forceinline__ float exp2_fast(float x) {
    x = fmaxf(x, -126.0f);
    float z = x + 12582912.0f;
    int   i = __float_as_int(z);
    float f = x - (z - 12582912.0f);
    float p = 1.33335581e-3f;
    p = fmaf(p, f, 9.61812910e-3f);
    p = fmaf(p, f, 5.55041087e-2f);
    p = fmaf(p, f, 2.40226507e-1f);
    p = fmaf(p, f, 6.93147181e-1f);
    p = fmaf(p, f, 1.0f);
    return __int_as_float(__float_as_int(p) + (i << 23));
}
__device__ __forceinline__ uint32_t smem_u32(const void* p) {
    uint32_t a;
    asm("{ .reg .u64 t; cvta.to.shared.u64 t, %1; cvt.u32.u64 %0, t; }"
        : "=r"(a) : "l"(p));
    return a;
}
#define CP_ASYNC16(dst, src)                                                  \
    asm volatile("cp.async.cg.shared.global [%0], [%1], 16;"                  \
                 :: "r"(dst), "l"(src) : "memory")
#define CP_COMMIT() asm volatile("cp.async.commit_group;" ::: "memory")
#define CP_WAIT(n)  asm volatile("cp.async.wait_group %0;" :: "n"(n) : "memory")

#define MMA_TF32(d, a, b)                                                     \
    asm volatile(                                                             \
        "mma.sync.aligned.m16n8k8.row.col.f32.tf32.tf32.f32 "                 \
        "{%0,%1,%2,%3}, {%4,%5,%6,%7}, {%8,%9}, {%0,%1,%2,%3};"               \
        : "+f"((d)[0]), "+f"((d)[1]), "+f"((d)[2]), "+f"((d)[3])              \
        : "r"((a)[0]), "r"((a)[1]), "r"((a)[2]), "r"((a)[3]),                 \
          "r"((b)[0]), "r"((b)[1]))

// ---------------------------------------------------------------------------
// Preprocess kernels
// ---------------------------------------------------------------------------
__global__ void round_tf32(const float4* __restrict__ src,
                           float4* __restrict__ dst, int n4)
{
    int i = blockIdx.x * blockDim.x + threadIdx.x;
    if (i >= n4) return;
    float4 v = src[i];
    dst[i] = make_float4(rtf(v.x), rtf(v.y), rtf(v.z), rtf(v.w));
}

// W [K][N] fp32 -> Wt [N][K] tf32-rounded fp32 (tiled transpose)
__global__ void wtrans_round(const float* __restrict__ W,
                             float* __restrict__ T, int K, int N)
{
    __shared__ float tile[32][33];
    const int k0 = blockIdx.y * 32, n0 = blockIdx.x * 32;
    const int tx = threadIdx.x, ty = threadIdx.y;   // 32 x 8
    #pragma unroll
    for (int i = 0; i < 32; i += 8)
        tile[ty + i][tx] = W[(size_t)(k0 + ty + i) * N + n0 + tx];
    __syncthreads();
    #pragma unroll
    for (int i = 0; i < 32; i += 8)
        T[(size_t)(n0 + ty + i) * K + k0 + tx] = rtf(tile[tx][ty + i]);
}

// ---------------------------------------------------------------------------
// TF32 GEMM: C[M,N] = A[M,K] @ Bt[N,K]^T + bias
// Block 256x128x32, 8 warps (4m x 2n), warp tile 64x64.
// A,Bt pre-rounded tf32; cp.async double-buffered staging; pad stride 36.
// ---------------------------------------------------------------------------
#define TG_BM 256
#define TG_BN 128
#define TG_BK 32
#define TSTR 36                        // floats per smem row (144 B)
#define SA_BYTES (TG_BM * TSTR * 4)    // 36864
#define SB_BYTES (TG_BN * TSTR * 4)    // 18432
#define TG_SMEM (2 * SA_BYTES + 2 * SB_BYTES)   // 110592

__device__ __forceinline__ void stage_tiles(uint32_t sA, uint32_t sB,
                                            const float* __restrict__ A,
                                            const float* __restrict__ Bt,
                                            int bm0, int bn0, int kc, int K,
                                            int tid)
{
    // A: 256 rows x 32 floats = 2048 16B units; 8 per thread
    #pragma unroll
    for (int it = 0; it < 8; it++) {
        const int u = tid + it * 256;
        const int row = u >> 3, seg = u & 7;
        const float* src = A + (size_t)(bm0 + row) * K + kc + seg * 4;
        CP_ASYNC16(sA + row * 144 + seg * 16, src);
    }
    // B: 128 rows x 32 floats = 1024 units; 4 per thread
    #pragma unroll
    for (int it = 0; it < 4; it++) {
        const int u = tid + it * 256;
        const int row = u >> 3, seg = u & 7;
        const float* src = Bt + (size_t)(bn0 + row) * K + kc + seg * 4;
        CP_ASYNC16(sB + row * 144 + seg * 16, src);
    }
    CP_COMMIT();
}

__global__ void __launch_bounds__(256, 1)
tgemm_tf32(const float* __restrict__ A, const float* __restrict__ Bt,
           const float* __restrict__ bias, float* __restrict__ C,
           int N, int K)
{
    extern __shared__ float sm[];
    const uint32_t smb = smem_u32(sm);
    const uint32_t sA[2] = { smb, smb + SA_BYTES };
    const uint32_t sB[2] = { smb + 2 * SA_BYTES, smb + 2 * SA_BYTES + SB_BYTES };
    float* fA[2] = { sm, sm + TG_BM * TSTR };
    float* fB[2] = { sm + 2 * TG_BM * TSTR, sm + 2 * TG_BM * TSTR + TG_BN * TSTR };

    const int tid  = threadIdx.x;
    const int lane = tid & 31, wid = tid >> 5;
    const int g = lane >> 2, t = lane & 3;
    const int wm = wid & 3, wn = wid >> 2;          // 4 m-warps x 2 n-warps
    const int bm0 = blockIdx.y * TG_BM, bn0 = blockIdx.x * TG_BN;

    float c[4][8][4];
    #pragma unroll
    for (int mt = 0; mt < 4; mt++)
        #pragma unroll
        for (int nt = 0; nt < 8; nt++)
            #pragma unroll
            for (int r = 0; r < 4; r++) c[mt][nt][r] = 0.f;

    const int NC = K / TG_BK;
    stage_tiles(sA[0], sB[0], A, Bt, bm0, bn0, 0, K, tid);
    if (NC > 1) stage_tiles(sA[1], sB[1], A, Bt, bm0, bn0, TG_BK, K, tid);

    for (int cix = 0; cix < NC; cix++) {
        const int b = cix & 1;
        if (cix + 1 < NC) CP_WAIT(1); else CP_WAIT(0);
        __syncthreads();

        const float* As_ = fA[b];
        const float* Bs_ = fB[b];
        #pragma unroll
        for (int ks = 0; ks < 4; ks++) {
            const int kk = ks * 8;
            unsigned a[4][4], bf[8][2];
            #pragma unroll
            for (int mt = 0; mt < 4; mt++) {
                const int r0 = (wm * 64 + mt * 16 + g) * TSTR + kk + t;
                a[mt][0] = __float_as_uint(As_[r0]);
                a[mt][1] = __float_as_uint(As_[r0 + 8 * TSTR]);
                a[mt][2] = __float_as_uint(As_[r0 + 4]);
                a[mt][3] = __float_as_uint(As_[r0 + 8 * TSTR + 4]);
            }
            #pragma unroll
            for (int nt = 0; nt < 8; nt++) {
                const int cb = (wn * 64 + nt * 8 + g) * TSTR + kk + t;
                bf[nt][0] = __float_as_uint(Bs_[cb]);
                bf[nt][1] = __float_as_uint(Bs_[cb + 4]);
            }
            #pragma unroll
            for (int mt = 0; mt < 4; mt++)
                #pragma unroll
                for (int nt = 0; nt < 8; nt++)
                    MMA_TF32(c[mt][nt], a[mt], bf[nt]);
        }
        __syncthreads();
        if (cix + 2 < NC)
            stage_tiles(sA[b], sB[b], A, Bt, bm0, bn0, (cix + 2) * TG_BK, K, tid);
    }

    // epilogue: bias + store
    #pragma unroll
    for (int mt = 0; mt < 4; mt++) {
        const int row = bm0 + wm * 64 + mt * 16 + g;
        #pragma unroll
        for (int nt = 0; nt < 8; nt++) {
            const int col = bn0 + wn * 64 + nt * 8 + 2 * t;
            float2 bv = *(const float2*)(bias + col);
            *(float2*)(C + (size_t)row * N + col) =
                make_float2(c[mt][nt][0] + bv.x, c[mt][nt][1] + bv.y);
            *(float2*)(C + (size_t)(row + 8) * N + col) =
                make_float2(c[mt][nt][2] + bv.x, c[mt][nt][3] + bv.y);
        }
    }
}

// ---------------------------------------------------------------------------
// TF32 tensor-core flash attention. 8 warps, 128 query rows per block.
// grid (S/128, B*H), 256 threads. Each warp owns 16 query rows.
// ---------------------------------------------------------------------------
#define KSTR 68
#define VSTR 72
#define QSCALE 0.18033688f   // (1/sqrt(64)) * log2(e)

__global__ void __launch_bounds__(256)
attn_tc_kernel(const float* __restrict__ qkv, float* __restrict__ attn)
{
    __shared__ float Ks[64 * KSTR];
    __shared__ float Vs[64 * VSTR];

    const int tid  = threadIdx.x;
    const int lane = tid & 31, wid = tid >> 5;
    const int g = lane >> 2, t = lane & 3;
    const int bh = blockIdx.y, b = bh >> 4, h = bh & 15;
    const int q0 = blockIdx.x * 128;
    const int rb = wid * 16;

    const float* base = qkv + (size_t)b * SS * D3;

    unsigned qa[8][4];
    {
        const float* qp = base + (size_t)q0 * D3 + h * HD;
        #pragma unroll
        for (int kc = 0; kc < 8; kc++) {
            const int cidx = kc * 8 + t;
            qa[kc][0] = rtu(qp[(size_t)(rb + g) * D3 + cidx] * QSCALE);
            qa[kc][1] = rtu(qp[(size_t)(rb + g + 8) * D3 + cidx] * QSCALE);
            qa[kc][2] = rtu(qp[(size_t)(rb + g) * D3 + cidx + 4] * QSCALE);
            qa[kc][3] = rtu(qp[(size_t)(rb + g + 8) * D3 + cidx + 4] * QSCALE);
        }
    }

    float o[8][4];
    #pragma unroll
    for (int nt = 0; nt < 8; nt++)
        #pragma unroll
        for (int r = 0; r < 4; r++) o[nt][r] = 0.f;

    float m0 = -1e30f, m1 = -1e30f, l0 = 0.f, l1 = 0.f;
    const int srcA = (lane & ~3) | (t >> 1);
    const int srcB = srcA + 2;

    for (int kt = 0; kt < SS; kt += 64) {
        __syncthreads();
        for (int j = tid; j < 1024; j += 256) {
            const int row = j >> 4, c4 = (j & 15) << 2;
            const float* kp = base + (size_t)(kt + row) * D3 + DD + h * HD + c4;
            float4 kv = *(const float4*)kp;
            float4 vv = *(const float4*)(kp + DD);
            *(float4*)&Ks[row * KSTR + c4] =
                make_float4(rtf(kv.x), rtf(kv.y), rtf(kv.z), rtf(kv.w));
            *(float4*)&Vs[row * VSTR + c4] =
                make_float4(rtf(vv.x), rtf(vv.y), rtf(vv.z), rtf(vv.w));
        }
        __syncthreads();

        float s[8][4];
        #pragma unroll
        for (int nt = 0; nt < 8; nt++)
            #pragma unroll
            for (int r = 0; r < 4; r++) s[nt][r] = 0.f;

        #pragma unroll
        for (int kc = 0; kc < 8; kc++) {
            #pragma unroll
            for (int nt = 0; nt < 8; nt++) {
                unsigned bf[2];
                bf[0] = __float_as_uint(Ks[(nt * 8 + g) * KSTR + kc * 8 + t]);
                bf[1] = __float_as_uint(Ks[(nt * 8 + g) * KSTR + kc * 8 + t + 4]);
                MMA_TF32(s[nt], qa[kc], bf);
            }
        }

        float cm0 = s[0][0], cm1 = s[0][2];
        #pragma unroll
        for (int nt = 0; nt < 8; nt++) {
            cm0 = fmaxf(cm0, fmaxf(s[nt][0], s[nt][1]));
            cm1 = fmaxf(cm1, fmaxf(s[nt][2], s[nt][3]));
        }
        cm0 = fmaxf(cm0, __shfl_xor_sync(0xffffffffu, cm0, 1));
        cm0 = fmaxf(cm0, __shfl_xor_sync(0xffffffffu, cm0, 2));
        cm1 = fmaxf(cm1, __shfl_xor_sync(0xffffffffu, cm1, 1));
        cm1 = fmaxf(cm1, __shfl_xor_sync(0xffffffffu, cm1, 2));

        const float mn0 = fmaxf(m0, cm0);
        const float mn1 = fmaxf(m1, cm1);
        const float corr0 = exp2_fast(m0 - mn0);
        const float corr1 = exp2_fast(m1 - mn1);
        m0 = mn0; m1 = mn1;

        float rs0 = 0.f, rs1 = 0.f;
        #pragma unroll
        for (int nt = 0; nt < 8; nt++) {
            float p;
            p = rtf(exp2_fast(s[nt][0] - mn0)); s[nt][0] = p; rs0 += p;
            p = rtf(exp2_fast(s[nt][1] - mn0)); s[nt][1] = p; rs0 += p;
            p = rtf(exp2_fast(s[nt][2] - mn1)); s[nt][2] = p; rs1 += p;
            p = rtf(exp2_fast(s[nt][3] - mn1)); s[nt][3] = p; rs1 += p;
            o[nt][0] *= corr0; o[nt][1] *= corr0;
            o[nt][2] *= corr1; o[nt][3] *= corr1;
        }
        rs0 += __shfl_xor_sync(0xffffffffu, rs0, 1);
        rs0 += __shfl_xor_sync(0xffffffffu, rs0, 2);
        rs1 += __shfl_xor_sync(0xffffffffu, rs1, 1);
        rs1 += __shfl_xor_sync(0xffffffffu, rs1, 2);
        l0 = l0 * corr0 + rs0;
        l1 = l1 * corr1 + rs1;

        #pragma unroll
        for (int kc = 0; kc < 8; kc++) {
            unsigned pa[4];
            {
                float v0 = __shfl_sync(0xffffffffu, s[kc][0], srcA);
                float v1 = __shfl_sync(0xffffffffu, s[kc][1], srcA);
                pa[0] = __float_as_uint((t & 1) ? v1 : v0);
                float v2 = __shfl_sync(0xffffffffu, s[kc][2], srcA);
                float v3 = __shfl_sync(0xffffffffu, s[kc][3], srcA);
                pa[1] = __float_as_uint((t & 1) ? v3 : v2);
                v0 = __shfl_sync(0xffffffffu, s[kc][0], srcB);
                v1 = __shfl_sync(0xffffffffu, s[kc][1], srcB);
                pa[2] = __float_as_uint((t & 1) ? v1 : v0);
                v2 = __shfl_sync(0xffffffffu, s[kc][2], srcB);
                v3 = __shfl_sync(0xffffffffu, s[kc][3], srcB);
                pa[3] = __float_as_uint((t & 1) ? v3 : v2);
            }
            #pragma unroll
            for (int nt = 0; nt < 8; nt++) {
                unsigned bf[2];
                bf[0] = __float_as_uint(Vs[(kc * 8 + t) * VSTR + nt * 8 + g]);
                bf[1] = __float_as_uint(Vs[(kc * 8 + t + 4) * VSTR + nt * 8 + g]);
                MMA_TF32(o[nt], pa, bf);
            }
        }
    }

    const float inv0 = 1.f / l0;
    const float inv1 = 1.f / l1;
    float* op = attn + (size_t)b * SS * DD + (size_t)(q0 + rb + g) * DD + h * HD;
    #pragma unroll
    for (int nt = 0; nt < 8; nt++) {
        const int col = nt * 8 + 2 * t;
        *(float2*)(op + col) =
            make_float2(o[nt][0] * inv0, o[nt][1] * inv0);
        *(float2*)(op + (size_t)8 * DD + col) =
            make_float2(o[nt][2] * inv1, o[nt][3] * inv1);
    }
}

// ---------------------------------------------------------------------------
// Launch
// ---------------------------------------------------------------------------
extern "C" void kernel_launch(void* const* d_in, const int* in_sizes, int n_in,
                              void* d_out, int out_size)
{
    const float* x     = (const float*)d_in[0];
    const float* W_qkv = (const float*)d_in[1];
    const float* b_qkv = (const float*)d_in[2];
    const float* W_out = (const float*)d_in[3];
    const float* b_out = (const float*)d_in[4];
    float* out = (float*)d_out;

    float *qkv, *attn, *xr, *ar, *wqt, *wot;
    cudaGetSymbolAddress((void**)&qkv,  g_qkv);
    cudaGetSymbolAddress((void**)&attn, g_attn);
    cudaGetSymbolAddress((void**)&xr,   g_xr);
    cudaGetSymbolAddress((void**)&ar,   g_ar);
    cudaGetSymbolAddress((void**)&wqt,  g_wqt);
    cudaGetSymbolAddress((void**)&wot,  g_wot);

    cudaFuncSetAttribute(tgemm_tf32,
                         cudaFuncAttributeMaxDynamicSharedMemorySize, TG_SMEM);

    // 0) preprocess: round x, transpose+round weights
    {
        int n4 = MM * DD / 4;
        round_tf32<<<(n4 + 255) / 256, 256>>>((const float4*)x, (float4*)xr, n4);
        dim3 tb(32, 8);
        wtrans_round<<<dim3(D3 / 32, DD / 32), tb>>>(W_qkv, wqt, DD, D3);
        wtrans_round<<<dim3(DD / 32, DD / 32), tb>>>(W_out, wot, DD, DD);
    }
    // 1) QKV projection: [4096,1024] @ [1024,3072] + bias
    tgemm_tf32<<<dim3(D3 / TG_BN, MM / TG_BM), 256, TG_SMEM>>>(
        xr, wqt, b_qkv, qkv, D3, DD);
    // 2) flash attention
    attn_tc_kernel<<<dim3(SS / 128, BB * HH), 256>>>(qkv, attn);
    // 3) round attn, then out projection
    {
        int n4 = MM * DD / 4;
        round_tf32<<<(n4 + 255) / 256, 256>>>((const float4*)attn, (float4*)ar, n4);
    }
    tgemm_tf32<<<dim3(DD / TG_BN, MM / TG_BM), 256, TG_SMEM>>>(
        ar, wot, b_out, out, DD, DD);
}

// round 6
// speedup vs baseline: 4.6614x; 1.0002x over previous
#include <cuda_runtime.h>
#include <math.h>
#include <stdint.h>

// Problem constants
#define BB 2
#define SS 2048
#define DD 1024
#define HH 16
#define HD 64
#define D3 (3 * DD)
#define MM (BB * SS)   // 4096

// ---------------------------------------------------------------------------
// Global scratch (no allocation allowed)
// ---------------------------------------------------------------------------
__device__ float g_qkv[MM * D3];   // [B,S,3D]; Q,K col-regions k-interleaved+tf32, V plain+tf32
__device__ float g_xr[MM * DD];    // x, tf32-rounded, k-interleaved
__device__ float g_ar[MM * DD];    // attn out, tf32-rounded, k-interleaved
__device__ float g_wqt[D3 * DD];   // W_qkv^T [N=3072][K=1024], rounded, k-interleaved
__device__ float g_wot[DD * DD];   // W_out^T [N=1024][K=1024], rounded, k-interleaved

// Interleave perm within 8-group: logical k -> position (k&3)*2 | (k>>2)
// => memory pos 2t holds logical t, pos 2t+1 holds logical t+4.
__device__ __forceinline__ int kperm(int k) {
    return (k & ~7) | (((k & 7) & 3) * 2) | (((k & 7) >> 2) & 1);
}

// ---------------------------------------------------------------------------
// Helpers
// ---------------------------------------------------------------------------
__device__ __forceinline__ float rtf(float x) {       // fp32 -> tf32 RN
    return __int_as_float(__float_as_int(x) + 0x1000);
}
__device__ __forceinline__ unsigned rtu(float x) {
    return (unsigned)(__float_as_int(x) + 0x1000);
}
__device__ __forceinline__ float ex2(float x) {       // MUFU exp2
    float r;
    asm("ex2.approx.f32 %0, %1;" : "=f"(r) : "f"(x));
    return r;
}
__device__ __forceinline__ uint32_t smem_u32(const void* p) {
    uint32_t a;
    asm("{ .reg .u64 t; cvta.to.shared.u64 t, %1; cvt.u32.u64 %0, t; }"
        : "=r"(a) : "l"(p));
    return a;
}
#define CP_ASYNC16(dst, src)                                                  \
    asm volatile("cp.async.cg.shared.global [%0], [%1], 16;"                  \
                 :: "r"(dst), "l"(src) : "memory")
#define CP_COMMIT() asm volatile("cp.async.commit_group;" ::: "memory")
#define CP_WAIT1()  asm volatile("cp.async.wait_group 1;" ::: "memory")
#define CP_WAIT2()  asm volatile("cp.async.wait_group 2;" ::: "memory")

#define MMA_TF32(d, a, b)                                                     \
    asm volatile(                                                             \
        "mma.sync.aligned.m16n8k8.row.col.f32.tf32.tf32.f32 "                 \
        "{%0,%1,%2,%3}, {%4,%5,%6,%7}, {%8,%9}, {%0,%1,%2,%3};"               \
        : "+f"((d)[0]), "+f"((d)[1]), "+f"((d)[2]), "+f"((d)[3])              \
        : "r"((a)[0]), "r"((a)[1]), "r"((a)[2]), "r"((a)[3]),                 \
          "r"((b)[0]), "r"((b)[1]))

// ---------------------------------------------------------------------------
// Preprocess kernels (round to tf32 + k-interleave)
// ---------------------------------------------------------------------------
__global__ void round_perm(const float4* __restrict__ src,
                           float* __restrict__ dst, int n4)
{
    int i = blockIdx.x * blockDim.x + threadIdx.x;
    if (i >= n4) return;
    float4 v = src[i];
    const int e = i * 4;
    const int base = e & ~7;
    const int half = (e >> 2) & 1;
    float* d = dst + base + half;
    d[0] = rtf(v.x); d[2] = rtf(v.y); d[4] = rtf(v.z); d[6] = rtf(v.w);
}

// W [K][N] -> Wt [N][K] rounded + k-interleaved
__global__ void wtrans_perm(const float* __restrict__ W,
                            float* __restrict__ T, int K, int N)
{
    __shared__ float tile[32][33];
    const int k0 = blockIdx.y * 32, n0 = blockIdx.x * 32;
    const int tx = threadIdx.x, ty = threadIdx.y;   // 32 x 8
    #pragma unroll
    for (int i = 0; i < 32; i += 8)
        tile[ty + i][tx] = W[(size_t)(k0 + ty + i) * N + n0 + tx];
    __syncthreads();
    const int kk = kperm(k0 + tx);
    #pragma unroll
    for (int i = 0; i < 32; i += 8)
        T[(size_t)(n0 + ty + i) * K + kk] = rtf(tile[tx][ty + i]);
}

// ---------------------------------------------------------------------------
// TF32 GEMM: C[M,N] = A[M,K] @ Bt[N,K]^T + bias
// Block 256x128x32, 8 warps (4m x 2n), warp tile 64x64.
// Operands pre-rounded + k-interleaved -> LDS.64 fragment loads.
// 3-stage cp.async ring. Per chunk: stage -> wait -> SYNC -> consume -> SYNC.
// (The sync AFTER the wait is load-bearing: wait_group only covers this
//  thread's copies; the trailing sync guards WAR on the 3-deep ring.)
// mode: 0 = plain output (final). 1 = qkv output: rtf; k-interleave if col<2048.
// ---------------------------------------------------------------------------
#define TG_BM 256
#define TG_BN 128
#define TG_BK 32
#define TSTR 40                           // floats per smem row (160 B)
#define SA_FLT (TG_BM * TSTR)             // 10240
#define SB_FLT (TG_BN * TSTR)             // 5120
#define STG_FLT (SA_FLT + SB_FLT)         // 15360
#define TG_SMEM (3 * STG_FLT * 4)         // 184320 bytes

__device__ __forceinline__ void g_stage(uint32_t sA, uint32_t sB,
                                        const float* __restrict__ A,
                                        const float* __restrict__ Bt,
                                        int bm0, int bn0, int kc, int K, int tid)
{
    #pragma unroll
    for (int it = 0; it < 8; it++) {
        const int u = tid + it * 256;
        const int row = u >> 3, seg = u & 7;
        CP_ASYNC16(sA + row * 160 + seg * 16,
                   A + (size_t)(bm0 + row) * K + kc + seg * 4);
    }
    #pragma unroll
    for (int it = 0; it < 4; it++) {
        const int u = tid + it * 256;
        const int row = u >> 3, seg = u & 7;
        CP_ASYNC16(sB + row * 160 + seg * 16,
                   Bt + (size_t)(bn0 + row) * K + kc + seg * 4);
    }
    CP_COMMIT();
}

__global__ void __launch_bounds__(256, 1)
tgemm_tf32(const float* __restrict__ A, const float* __restrict__ Bt,
           const float* __restrict__ bias, float* __restrict__ C,
           int N, int K, int mode)
{
    extern __shared__ float sm[];
    const uint32_t smb = smem_u32(sm);

    const int tid  = threadIdx.x;
    const int lane = tid & 31, wid = tid >> 5;
    const int g = lane >> 2, t = lane & 3;
    const int wm = wid & 3, wn = wid >> 2;
    const int bm0 = blockIdx.y * TG_BM, bn0 = blockIdx.x * TG_BN;

    float c[4][8][4];
    #pragma unroll
    for (int mt = 0; mt < 4; mt++)
        #pragma unroll
        for (int nt = 0; nt < 8; nt++)
            #pragma unroll
            for (int r = 0; r < 4; r++) c[mt][nt][r] = 0.f;

    const int NC = K / TG_BK;
    g_stage(smb, smb + SA_FLT * 4, A, Bt, bm0, bn0, 0, K, tid);
    g_stage(smb + STG_FLT * 4, smb + (STG_FLT + SA_FLT) * 4,
            A, Bt, bm0, bn0, TG_BK, K, tid);

    for (int cix = 0; cix < NC; cix++) {
        if (cix + 2 < NC) {
            const int sb = (cix + 2) % 3;
            g_stage(smb + (sb * STG_FLT) * 4, smb + (sb * STG_FLT + SA_FLT) * 4,
                    A, Bt, bm0, bn0, (cix + 2) * TG_BK, K, tid);
        } else {
            CP_COMMIT();
        }
        CP_WAIT2();
        __syncthreads();            // all threads' copies for chunk cix visible

        const float* As_ = sm + (cix % 3) * STG_FLT;
        const float* Bs_ = As_ + SA_FLT;
        #pragma unroll
        for (int ks = 0; ks < 4; ks++) {
            const int kk = ks * 8;
            unsigned a[4][4], bf[8][2];
            #pragma unroll
            for (int mt = 0; mt < 4; mt++) {
                const int r0 = (wm * 64 + mt * 16 + g) * TSTR + kk + 2 * t;
                uint2 v0 = *(const uint2*)(As_ + r0);            // {t, t+4}
                uint2 v1 = *(const uint2*)(As_ + r0 + 8 * TSTR);
                a[mt][0] = v0.x; a[mt][2] = v0.y;
                a[mt][1] = v1.x; a[mt][3] = v1.y;
            }
            #pragma unroll
            for (int nt = 0; nt < 8; nt++) {
                const int cb = (wn * 64 + nt * 8 + g) * TSTR + kk + 2 * t;
                uint2 v = *(const uint2*)(Bs_ + cb);
                bf[nt][0] = v.x; bf[nt][1] = v.y;
            }
            #pragma unroll
            for (int mt = 0; mt < 4; mt++)
                #pragma unroll
                for (int nt = 0; nt < 8; nt++)
                    MMA_TF32(c[mt][nt], a[mt], bf[nt]);
        }
        __syncthreads();            // WAR guard: ring buffer reuse at cix+1
    }

    // epilogue
    const bool ilv = (mode == 1) && (bn0 < 2048);     // Q/K regions interleaved
    const int p0 = 2 * (2 * t & 3) + (t >> 1);        // kperm(2t)   in-group
    const int p1 = 2 * ((2 * t + 1) & 3) + (t >> 1);  // kperm(2t+1)
    #pragma unroll
    for (int mt = 0; mt < 4; mt++) {
        const int row = bm0 + wm * 64 + mt * 16 + g;
        #pragma unroll
        for (int nt = 0; nt < 8; nt++) {
            const int col = bn0 + wn * 64 + nt * 8 + 2 * t;   // logical
            float2 bv = *(const float2*)(bias + col);
            float v00 = c[mt][nt][0] + bv.x, v01 = c[mt][nt][1] + bv.y;
            float v10 = c[mt][nt][2] + bv.x, v11 = c[mt][nt][3] + bv.y;
            if (mode == 1) {
                v00 = rtf(v00); v01 = rtf(v01); v10 = rtf(v10); v11 = rtf(v11);
            }
            float* r0p = C + (size_t)row * N;
            float* r1p = C + (size_t)(row + 8) * N;
            if (ilv) {
                const int gb = bn0 + wn * 64 + nt * 8;
                r0p[gb + p0] = v00; r0p[gb + p1] = v01;
                r1p[gb + p0] = v10; r1p[gb + p1] = v11;
            } else {
                *(float2*)(r0p + col) = make_float2(v00, v01);
                *(float2*)(r1p + col) = make_float2(v10, v11);
            }
        }
    }
}

// ---------------------------------------------------------------------------
// TF32 flash attention. 8 warps, 128 query rows/block, 64-key tiles.
// Q/K k-interleaved in gmem (LDS.64 frags); V plain. cp.async double-buffered
// K/V. P through per-warp smem (no shuffles). MUFU exp2. Output written
// rounded + interleaved straight to g_ar (feeds GEMM2).
// grid (S/128, B*H), 256 threads.
// ---------------------------------------------------------------------------
#define KVSTR 72                            // floats per K/V smem row (288 B)
#define PSTR  72
#define KV_FLT (64 * KVSTR)                 // 4608 floats per tile
#define AT_SMEM ((4 * KV_FLT + 8 * 16 * PSTR) * 4)   // 110592 B
#define QSCALE 0.18033688f                  // (1/sqrt(64)) * log2(e)

__device__ __forceinline__ void a_stage(uint32_t kb, uint32_t vb,
                                        const float* __restrict__ base,
                                        int kt, int h, int tid)
{
    const float* kg = base + DD + h * HD;
    const float* vg = base + 2 * DD + h * HD;
    #pragma unroll
    for (int it = 0; it < 4; it++) {
        const int u = tid + it * 256;
        const int row = u >> 4, cseg = u & 15;
        CP_ASYNC16(kb + row * 288 + cseg * 16,
                   kg + (size_t)(kt + row) * D3 + cseg * 4);
    }
    #pragma unroll
    for (int it = 0; it < 4; it++) {
        const int u = tid + it * 256;
        const int row = u >> 4, cseg = u & 15;
        CP_ASYNC16(vb + row * 288 + cseg * 16,
                   vg + (size_t)(kt + row) * D3 + cseg * 4);
    }
    CP_COMMIT();
}

__global__ void __launch_bounds__(256, 1)
attn_tc_kernel(const float* __restrict__ qkv, float* __restrict__ outA)
{
    extern __shared__ float sm[];
    const uint32_t smb = smem_u32(sm);
    float* Ksb[2] = { sm,              sm + 2 * KV_FLT };
    float* Vsb[2] = { sm + KV_FLT,     sm + 3 * KV_FLT };
    const uint32_t kaddr[2] = { smb, smb + 2 * KV_FLT * 4 };
    const uint32_t vaddr[2] = { smb + KV_FLT * 4, smb + 3 * KV_FLT * 4 };

    const int tid  = threadIdx.x;
    const int lane = tid & 31, wid = tid >> 5;
    const int g = lane >> 2, t = lane & 3;
    const int bh = blockIdx.y, b = bh >> 4, h = bh & 15;
    const int q0 = blockIdx.x * 128;
    const int rb = wid * 16;

    float* Pw = sm + 4 * KV_FLT + wid * 16 * PSTR;

    const float* base = qkv + (size_t)b * SS * D3;

    a_stage(kaddr[0], vaddr[0], base, 0, h, tid);

    // Q fragments (gmem tf32-rounded + interleaved: pos 2t,2t+1 = logical t,t+4)
    unsigned qa[8][4];
    {
        const float* qp = base + (size_t)q0 * D3 + h * HD;
        #pragma unroll
        for (int kc = 0; kc < 8; kc++) {
            float2 v0 = *(const float2*)(qp + (size_t)(rb + g) * D3 + kc * 8 + 2 * t);
            float2 v1 = *(const float2*)(qp + (size_t)(rb + g + 8) * D3 + kc * 8 + 2 * t);
            qa[kc][0] = rtu(v0.x * QSCALE); qa[kc][2] = rtu(v0.y * QSCALE);
            qa[kc][1] = rtu(v1.x * QSCALE); qa[kc][3] = rtu(v1.y * QSCALE);
        }
    }

    float o[8][4];
    #pragma unroll
    for (int nt = 0; nt < 8; nt++)
        #pragma unroll
        for (int r = 0; r < 4; r++) o[nt][r] = 0.f;
    float m0 = -1e30f, m1 = -1e30f, l0 = 0.f, l1 = 0.f;

    const int NT = SS / 64;   // 32
    for (int i = 0; i < NT; i++) {
        const int buf = i & 1;
        __syncthreads();                      // WAR: prev consume of buf^1 done
        if (i + 1 < NT)
            a_stage(kaddr[buf ^ 1], vaddr[buf ^ 1], base, (i + 1) * 64, h, tid);
        else
            CP_COMMIT();
        CP_WAIT1();
        __syncthreads();                      // RAW: all copies of buf visible

        const float* Ks = Ksb[buf];
        const float* Vs = Vsb[buf];

        // S = Q K^T
        float s[8][4];
        #pragma unroll
        for (int nt = 0; nt < 8; nt++)
            #pragma unroll
            for (int r = 0; r < 4; r++) s[nt][r] = 0.f;
        #pragma unroll
        for (int kc = 0; kc < 8; kc++) {
            #pragma unroll
            for (int nt = 0; nt < 8; nt++) {
                uint2 kv = *(const uint2*)(Ks + (nt * 8 + g) * KVSTR + kc * 8 + 2 * t);
                unsigned bf[2] = { kv.x, kv.y };
                MMA_TF32(s[nt], qa[kc], bf);
            }
        }

        // online softmax (base-2; rows rb+g, rb+g+8)
        float cm0 = s[0][0], cm1 = s[0][2];
        #pragma unroll
        for (int nt = 0; nt < 8; nt++) {
            cm0 = fmaxf(cm0, fmaxf(s[nt][0], s[nt][1]));
            cm1 = fmaxf(cm1, fmaxf(s[nt][2], s[nt][3]));
        }
        cm0 = fmaxf(cm0, __shfl_xor_sync(0xffffffffu, cm0, 1));
        cm0 = fmaxf(cm0, __shfl_xor_sync(0xffffffffu, cm0, 2));
        cm1 = fmaxf(cm1, __shfl_xor_sync(0xffffffffu, cm1, 1));
        cm1 = fmaxf(cm1, __shfl_xor_sync(0xffffffffu, cm1, 2));
        const float mn0 = fmaxf(m0, cm0);
        const float mn1 = fmaxf(m1, cm1);
        const float corr0 = ex2(m0 - mn0);
        const float corr1 = ex2(m1 - mn1);
        m0 = mn0; m1 = mn1;

        float rs0 = 0.f, rs1 = 0.f;
        #pragma unroll
        for (int nt = 0; nt < 8; nt++) {
            float p;
            p = rtf(ex2(s[nt][0] - mn0)); s[nt][0] = p; rs0 += p;
            p = rtf(ex2(s[nt][1] - mn0)); s[nt][1] = p; rs0 += p;
            p = rtf(ex2(s[nt][2] - mn1)); s[nt][2] = p; rs1 += p;
            p = rtf(ex2(s[nt][3] - mn1)); s[nt][3] = p; rs1 += p;
            o[nt][0] *= corr0; o[nt][1] *= corr0;
            o[nt][2] *= corr1; o[nt][3] *= corr1;
        }
        rs0 += __shfl_xor_sync(0xffffffffu, rs0, 1);
        rs0 += __shfl_xor_sync(0xffffffffu, rs0, 2);
        rs1 += __shfl_xor_sync(0xffffffffu, rs1, 1);
        rs1 += __shfl_xor_sync(0xffffffffu, rs1, 2);
        l0 = l0 * corr0 + rs0;
        l1 = l1 * corr1 + rs1;

        // P -> per-warp smem (plain key layout), then PV via a-frag LDS
        #pragma unroll
        for (int nt = 0; nt < 8; nt++) {
            *(float2*)(Pw + g * PSTR + nt * 8 + 2 * t) =
                make_float2(s[nt][0], s[nt][1]);
            *(float2*)(Pw + (g + 8) * PSTR + nt * 8 + 2 * t) =
                make_float2(s[nt][2], s[nt][3]);
        }
        __syncwarp();
        #pragma unroll
        for (int kc = 0; kc < 8; kc++) {
            unsigned pa[4];
            pa[0] = __float_as_uint(Pw[g * PSTR + kc * 8 + t]);
            pa[1] = __float_as_uint(Pw[(g + 8) * PSTR + kc * 8 + t]);
            pa[2] = __float_as_uint(Pw[g * PSTR + kc * 8 + t + 4]);
            pa[3] = __float_as_uint(Pw[(g + 8) * PSTR + kc * 8 + t + 4]);
            #pragma unroll
            for (int nt = 0; nt < 8; nt++) {
                unsigned bf[2];
                bf[0] = __float_as_uint(Vs[(kc * 8 + t) * KVSTR + nt * 8 + g]);
                bf[1] = __float_as_uint(Vs[(kc * 8 + t + 4) * KVSTR + nt * 8 + g]);
                MMA_TF32(o[nt], pa, bf);
            }
        }
        __syncwarp();   // P reused next tile
    }

    // epilogue: normalize, round, interleave -> g_ar (GEMM2's A operand)
    const float inv0 = 1.f / l0;
    const float inv1 = 1.f / l1;
    const int p0 = 2 * (2 * t & 3) + (t >> 1);
    const int p1 = 2 * ((2 * t + 1) & 3) + (t >> 1);
    float* op0 = outA + (size_t)b * SS * DD + (size_t)(q0 + rb + g) * DD + h * HD;
    float* op1 = op0 + (size_t)8 * DD;
    #pragma unroll
    for (int nt = 0; nt < 8; nt++) {
        const int gb = nt * 8;
        op0[gb + p0] = rtf(o[nt][0] * inv0);
        op0[gb + p1] = rtf(o[nt][1] * inv0);
        op1[gb + p0] = rtf(o[nt][2] * inv1);
        op1[gb + p1] = rtf(o[nt][3] * inv1);
    }
}

// ---------------------------------------------------------------------------
// Launch
// ---------------------------------------------------------------------------
extern "C" void kernel_launch(void* const* d_in, const int* in_sizes, int n_in,
                              void* d_out, int out_size)
{
    const float* x     = (const float*)d_in[0];
    const float* W_qkv = (const float*)d_in[1];
    const float* b_qkv = (const float*)d_in[2];
    const float* W_out = (const float*)d_in[3];
    const float* b_out = (const float*)d_in[4];
    float* out = (float*)d_out;

    float *qkv, *xr, *ar, *wqt, *wot;
    cudaGetSymbolAddress((void**)&qkv, g_qkv);
    cudaGetSymbolAddress((void**)&xr,  g_xr);
    cudaGetSymbolAddress((void**)&ar,  g_ar);
    cudaGetSymbolAddress((void**)&wqt, g_wqt);
    cudaGetSymbolAddress((void**)&wot, g_wot);

    cudaFuncSetAttribute(tgemm_tf32,
                         cudaFuncAttributeMaxDynamicSharedMemorySize, TG_SMEM);
    cudaFuncSetAttribute(attn_tc_kernel,
                         cudaFuncAttributeMaxDynamicSharedMemorySize, AT_SMEM);

    // 0) preprocess
    {
        int n4 = MM * DD / 4;
        round_perm<<<(n4 + 255) / 256, 256>>>((const float4*)x, xr, n4);
        dim3 tb(32, 8);
        wtrans_perm<<<dim3(D3 / 32, DD / 32), tb>>>(W_qkv, wqt, DD, D3);
        wtrans_perm<<<dim3(DD / 32, DD / 32), tb>>>(W_out, wot, DD, DD);
    }
    // 1) QKV projection (mode 1: rtf; interleave Q/K col regions)
    tgemm_tf32<<<dim3(D3 / TG_BN, MM / TG_BM), 256, TG_SMEM>>>(
        xr, wqt, b_qkv, qkv, D3, DD, 1);
    // 2) flash attention -> g_ar (rounded + interleaved)
    attn_tc_kernel<<<dim3(SS / 128, BB * HH), 256, AT_SMEM>>>(qkv, ar);
    // 3) output projection (mode 0: plain final output)
    tgemm_tf32<<<dim3(DD / TG_BN, MM / TG_BM), 256, TG_SMEM>>>(
        ar, wot, b_out, out, DD, DD, 0);
}

// round 8
// speedup vs baseline: 5.7107x; 1.2251x over previous
#include <cuda_runtime.h>
#include <math.h>
#include <stdint.h>

// Problem constants
#define BB 2
#define SS 2048
#define DD 1024
#define HH 16
#define HD 64
#define D3 (3 * DD)
#define MM (BB * SS)   // 4096

// ---------------------------------------------------------------------------
// Global scratch (no allocation allowed)
// ---------------------------------------------------------------------------
__device__ float g_qkv[MM * D3];   // [B,S,3D]; Q,K col-regions k-interleaved+tf32, V plain+tf32
__device__ float g_xr[MM * DD];    // x, tf32-rounded, k-interleaved
__device__ float g_ar[MM * DD];    // attn out, tf32-rounded, k-interleaved
__device__ float g_wqt[D3 * DD];   // W_qkv^T [N=3072][K=1024], rounded, k-interleaved
__device__ float g_wot[DD * DD];   // W_out^T [N=1024][K=1024], rounded, k-interleaved

// Interleave perm within 8-group: logical k -> position (k&3)*2 | (k>>2)
__device__ __forceinline__ int kperm(int k) {
    return (k & ~7) | (((k & 7) & 3) * 2) | (((k & 7) >> 2) & 1);
}

// ---------------------------------------------------------------------------
// Helpers
// ---------------------------------------------------------------------------
__device__ __forceinline__ float rtf(float x) {       // fp32 -> tf32 RN
    return __int_as_float(__float_as_int(x) + 0x1000);
}
__device__ __forceinline__ unsigned rtu(float x) {
    return (unsigned)(__float_as_int(x) + 0x1000);
}
__device__ __forceinline__ float ex2(float x) {       // MUFU exp2
    float r;
    asm("ex2.approx.f32 %0, %1;" : "=f"(r) : "f"(x));
    return r;
}
__device__ __forceinline__ uint32_t smem_u32(const void* p) {
    uint32_t a;
    asm("{ .reg .u64 t; cvta.to.shared.u64 t, %1; cvt.u32.u64 %0, t; }"
        : "=r"(a) : "l"(p));
    return a;
}
#define CP_ASYNC16(dst, src)                                                  \
    asm volatile("cp.async.cg.shared.global [%0], [%1], 16;"                  \
                 :: "r"(dst), "l"(src) : "memory")
#define CP_COMMIT() asm volatile("cp.async.commit_group;" ::: "memory")
#define CP_WAIT1()  asm volatile("cp.async.wait_group 1;" ::: "memory")
#define CP_WAIT2()  asm volatile("cp.async.wait_group 2;" ::: "memory")

#define MMA_TF32(d, a, b)                                                     \
    asm volatile(                                                             \
        "mma.sync.aligned.m16n8k8.row.col.f32.tf32.tf32.f32 "                 \
        "{%0,%1,%2,%3}, {%4,%5,%6,%7}, {%8,%9}, {%0,%1,%2,%3};"               \
        : "+f"((d)[0]), "+f"((d)[1]), "+f"((d)[2]), "+f"((d)[3])              \
        : "r"((a)[0]), "r"((a)[1]), "r"((a)[2]), "r"((a)[3]),                 \
          "r"((b)[0]), "r"((b)[1]))

// ---------------------------------------------------------------------------
// Preprocess kernels (round to tf32 + k-interleave)
// ---------------------------------------------------------------------------
__global__ void round_perm(const float4* __restrict__ src,
                           float* __restrict__ dst, int n4)
{
    int i = blockIdx.x * blockDim.x + threadIdx.x;
    if (i >= n4) return;
    float4 v = src[i];
    const int e = i * 4;
    const int base = e & ~7;
    const int half = (e >> 2) & 1;
    float* d = dst + base + half;
    d[0] = rtf(v.x); d[2] = rtf(v.y); d[4] = rtf(v.z); d[6] = rtf(v.w);
}

// W [K][N] -> Wt [N][K] rounded + k-interleaved
__global__ void wtrans_perm(const float* __restrict__ W,
                            float* __restrict__ T, int K, int N)
{
    __shared__ float tile[32][33];
    const int k0 = blockIdx.y * 32, n0 = blockIdx.x * 32;
    const int tx = threadIdx.x, ty = threadIdx.y;   // 32 x 8
    #pragma unroll
    for (int i = 0; i < 32; i += 8)
        tile[ty + i][tx] = W[(size_t)(k0 + ty + i) * N + n0 + tx];
    __syncthreads();
    const int kk = kperm(k0 + tx);
    #pragma unroll
    for (int i = 0; i < 32; i += 8)
        T[(size_t)(n0 + ty + i) * K + kk] = rtf(tile[tx][ty + i]);
}

// ---------------------------------------------------------------------------
// TF32 GEMM (unchanged from round 6): C[M,N] = A[M,K] @ Bt[N,K]^T + bias
// ---------------------------------------------------------------------------
#define TG_BM 256
#define TG_BN 128
#define TG_BK 32
#define TSTR 40
#define SA_FLT (TG_BM * TSTR)
#define SB_FLT (TG_BN * TSTR)
#define STG_FLT (SA_FLT + SB_FLT)
#define TG_SMEM (3 * STG_FLT * 4)

__device__ __forceinline__ void g_stage(uint32_t sA, uint32_t sB,
                                        const float* __restrict__ A,
                                        const float* __restrict__ Bt,
                                        int bm0, int bn0, int kc, int K, int tid)
{
    #pragma unroll
    for (int it = 0; it < 8; it++) {
        const int u = tid + it * 256;
        const int row = u >> 3, seg = u & 7;
        CP_ASYNC16(sA + row * 160 + seg * 16,
                   A + (size_t)(bm0 + row) * K + kc + seg * 4);
    }
    #pragma unroll
    for (int it = 0; it < 4; it++) {
        const int u = tid + it * 256;
        const int row = u >> 3, seg = u & 7;
        CP_ASYNC16(sB + row * 160 + seg * 16,
                   Bt + (size_t)(bn0 + row) * K + kc + seg * 4);
    }
    CP_COMMIT();
}

__global__ void __launch_bounds__(256, 1)
tgemm_tf32(const float* __restrict__ A, const float* __restrict__ Bt,
           const float* __restrict__ bias, float* __restrict__ C,
           int N, int K, int mode)
{
    extern __shared__ float sm[];
    const uint32_t smb = smem_u32(sm);

    const int tid  = threadIdx.x;
    const int lane = tid & 31, wid = tid >> 5;
    const int g = lane >> 2, t = lane & 3;
    const int wm = wid & 3, wn = wid >> 2;
    const int bm0 = blockIdx.y * TG_BM, bn0 = blockIdx.x * TG_BN;

    float c[4][8][4];
    #pragma unroll
    for (int mt = 0; mt < 4; mt++)
        #pragma unroll
        for (int nt = 0; nt < 8; nt++)
            #pragma unroll
            for (int r = 0; r < 4; r++) c[mt][nt][r] = 0.f;

    const int NC = K / TG_BK;
    g_stage(smb, smb + SA_FLT * 4, A, Bt, bm0, bn0, 0, K, tid);
    g_stage(smb + STG_FLT * 4, smb + (STG_FLT + SA_FLT) * 4,
            A, Bt, bm0, bn0, TG_BK, K, tid);

    for (int cix = 0; cix < NC; cix++) {
        if (cix + 2 < NC) {
            const int sb = (cix + 2) % 3;
            g_stage(smb + (sb * STG_FLT) * 4, smb + (sb * STG_FLT + SA_FLT) * 4,
                    A, Bt, bm0, bn0, (cix + 2) * TG_BK, K, tid);
        } else {
            CP_COMMIT();
        }
        CP_WAIT2();
        __syncthreads();

        const float* As_ = sm + (cix % 3) * STG_FLT;
        const float* Bs_ = As_ + SA_FLT;
        #pragma unroll
        for (int ks = 0; ks < 4; ks++) {
            const int kk = ks * 8;
            unsigned a[4][4], bf[8][2];
            #pragma unroll
            for (int mt = 0; mt < 4; mt++) {
                const int r0 = (wm * 64 + mt * 16 + g) * TSTR + kk + 2 * t;
                uint2 v0 = *(const uint2*)(As_ + r0);
                uint2 v1 = *(const uint2*)(As_ + r0 + 8 * TSTR);
                a[mt][0] = v0.x; a[mt][2] = v0.y;
                a[mt][1] = v1.x; a[mt][3] = v1.y;
            }
            #pragma unroll
            for (int nt = 0; nt < 8; nt++) {
                const int cb = (wn * 64 + nt * 8 + g) * TSTR + kk + 2 * t;
                uint2 v = *(const uint2*)(Bs_ + cb);
                bf[nt][0] = v.x; bf[nt][1] = v.y;
            }
            #pragma unroll
            for (int mt = 0; mt < 4; mt++)
                #pragma unroll
                for (int nt = 0; nt < 8; nt++)
                    MMA_TF32(c[mt][nt], a[mt], bf[nt]);
        }
        __syncthreads();
    }

    const bool ilv = (mode == 1) && (bn0 < 2048);
    const int p0 = 2 * (2 * t & 3) + (t >> 1);
    const int p1 = 2 * ((2 * t + 1) & 3) + (t >> 1);
    #pragma unroll
    for (int mt = 0; mt < 4; mt++) {
        const int row = bm0 + wm * 64 + mt * 16 + g;
        #pragma unroll
        for (int nt = 0; nt < 8; nt++) {
            const int col = bn0 + wn * 64 + nt * 8 + 2 * t;
            float2 bv = *(const float2*)(bias + col);
            float v00 = c[mt][nt][0] + bv.x, v01 = c[mt][nt][1] + bv.y;
            float v10 = c[mt][nt][2] + bv.x, v11 = c[mt][nt][3] + bv.y;
            if (mode == 1) {
                v00 = rtf(v00); v01 = rtf(v01); v10 = rtf(v10); v11 = rtf(v11);
            }
            float* r0p = C + (size_t)row * N;
            float* r1p = C + (size_t)(row + 8) * N;
            if (ilv) {
                const int gb = bn0 + wn * 64 + nt * 8;
                r0p[gb + p0] = v00; r0p[gb + p1] = v01;
                r1p[gb + p0] = v10; r1p[gb + p1] = v11;
            } else {
                *(float2*)(r0p + col) = make_float2(v00, v01);
                *(float2*)(r1p + col) = make_float2(v10, v11);
            }
        }
    }
}

// ---------------------------------------------------------------------------
// TF32 flash attention, 32 q-rows per warp (2 MMA row-groups).
// 8 warps, 256 query rows/block, 64-key tiles. K frags + V frags + staging
// amortized over 2x rows; all dependency chains have 2x independent ILP.
// grid (S/256, B*H), 256 threads.
// ---------------------------------------------------------------------------
#define KVSTR 72
#define PSTR  72
#define KV_FLT (64 * KVSTR)                      // 4608 floats per tile
#define AT_SMEM ((4 * KV_FLT + 8 * 32 * PSTR) * 4)   // 147456 B
#define QSCALE 0.18033688f                       // (1/sqrt(64)) * log2(e)

__device__ __forceinline__ void a_stage(uint32_t kb, uint32_t vb,
                                        const float* __restrict__ base,
                                        int kt, int h, int tid)
{
    const float* kg = base + DD + h * HD;
    const float* vg = base + 2 * DD + h * HD;
    #pragma unroll
    for (int it = 0; it < 4; it++) {
        const int u = tid + it * 256;
        const int row = u >> 4, cseg = u & 15;
        CP_ASYNC16(kb + row * 288 + cseg * 16,
                   kg + (size_t)(kt + row) * D3 + cseg * 4);
    }
    #pragma unroll
    for (int it = 0; it < 4; it++) {
        const int u = tid + it * 256;
        const int row = u >> 4, cseg = u & 15;
        CP_ASYNC16(vb + row * 288 + cseg * 16,
                   vg + (size_t)(kt + row) * D3 + cseg * 4);
    }
    CP_COMMIT();
}

__global__ void __launch_bounds__(256, 1)
attn_tc_kernel(const float* __restrict__ qkv, float* __restrict__ outA)
{
    extern __shared__ float sm[];
    const uint32_t smb = smem_u32(sm);
    float* Ksb[2] = { sm,          sm + 2 * KV_FLT };
    float* Vsb[2] = { sm + KV_FLT, sm + 3 * KV_FLT };
    const uint32_t kaddr[2] = { smb, smb + 2 * KV_FLT * 4 };
    const uint32_t vaddr[2] = { smb + KV_FLT * 4, smb + 3 * KV_FLT * 4 };

    const int tid  = threadIdx.x;
    const int lane = tid & 31, wid = tid >> 5;
    const int g = lane >> 2, t = lane & 3;
    const int bh = blockIdx.y, b = bh >> 4, h = bh & 15;
    const int q0 = blockIdx.x * 256;
    const int rb = wid * 32;                    // warp's 32-row base

    float* Pw = sm + 4 * KV_FLT + wid * 32 * PSTR;

    const float* base = qkv + (size_t)b * SS * D3;

    a_stage(kaddr[0], vaddr[0], base, 0, h, tid);

    // Q fragments: 2 row-groups x 8 k-chunks (gmem tf32-rounded + interleaved)
    unsigned qa[2][8][4];
    {
        const float* qp = base + (size_t)q0 * D3 + h * HD;
        #pragma unroll
        for (int u = 0; u < 2; u++) {
            const int r0 = rb + u * 16 + g;
            #pragma unroll
            for (int kc = 0; kc < 8; kc++) {
                float2 v0 = *(const float2*)(qp + (size_t)r0 * D3 + kc * 8 + 2 * t);
                float2 v1 = *(const float2*)(qp + (size_t)(r0 + 8) * D3 + kc * 8 + 2 * t);
                qa[u][kc][0] = rtu(v0.x * QSCALE); qa[u][kc][2] = rtu(v0.y * QSCALE);
                qa[u][kc][1] = rtu(v1.x * QSCALE); qa[u][kc][3] = rtu(v1.y * QSCALE);
            }
        }
    }

    float o[2][8][4];
    #pragma unroll
    for (int u = 0; u < 2; u++)
        #pragma unroll
        for (int nt = 0; nt < 8; nt++)
            #pragma unroll
            for (int r = 0; r < 4; r++) o[u][nt][r] = 0.f;
    float m[2][2] = { { -1e30f, -1e30f }, { -1e30f, -1e30f } };
    float l[2][2] = { { 0.f, 0.f }, { 0.f, 0.f } };

    const int NT = SS / 64;   // 32
    for (int i = 0; i < NT; i++) {
        const int buf = i & 1;
        __syncthreads();                      // WAR: prev consume of buf^1 done
        if (i + 1 < NT)
            a_stage(kaddr[buf ^ 1], vaddr[buf ^ 1], base, (i + 1) * 64, h, tid);
        else
            CP_COMMIT();
        CP_WAIT1();
        __syncthreads();                      // RAW: all copies of buf visible

        const float* Ks = Ksb[buf];
        const float* Vs = Vsb[buf];

        // S = Q K^T : K fragments shared across both row-groups
        float s[2][8][4];
        #pragma unroll
        for (int u = 0; u < 2; u++)
            #pragma unroll
            for (int nt = 0; nt < 8; nt++)
                #pragma unroll
                for (int r = 0; r < 4; r++) s[u][nt][r] = 0.f;
        #pragma unroll
        for (int kc = 0; kc < 8; kc++) {
            #pragma unroll
            for (int nt = 0; nt < 8; nt++) {
                uint2 kv = *(const uint2*)(Ks + (nt * 8 + g) * KVSTR + kc * 8 + 2 * t);
                unsigned bf[2] = { kv.x, kv.y };
                MMA_TF32(s[0][nt], qa[0][kc], bf);
                MMA_TF32(s[1][nt], qa[1][kc], bf);
            }
        }

        // online softmax per row-group (base-2 domain)
        #pragma unroll
        for (int u = 0; u < 2; u++) {
            float cm0 = s[u][0][0], cm1 = s[u][0][2];
            #pragma unroll
            for (int nt = 0; nt < 8; nt++) {
                cm0 = fmaxf(cm0, fmaxf(s[u][nt][0], s[u][nt][1]));
                cm1 = fmaxf(cm1, fmaxf(s[u][nt][2], s[u][nt][3]));
            }
            cm0 = fmaxf(cm0, __shfl_xor_sync(0xffffffffu, cm0, 1));
            cm0 = fmaxf(cm0, __shfl_xor_sync(0xffffffffu, cm0, 2));
            cm1 = fmaxf(cm1, __shfl_xor_sync(0xffffffffu, cm1, 1));
            cm1 = fmaxf(cm1, __shfl_xor_sync(0xffffffffu, cm1, 2));
            const float mn0 = fmaxf(m[u][0], cm0);
            const float mn1 = fmaxf(m[u][1], cm1);
            const float corr0 = ex2(m[u][0] - mn0);
            const float corr1 = ex2(m[u][1] - mn1);
            m[u][0] = mn0; m[u][1] = mn1;

            float rs0 = 0.f, rs1 = 0.f;
            #pragma unroll
            for (int nt = 0; nt < 8; nt++) {
                float p;
                p = rtf(ex2(s[u][nt][0] - mn0)); s[u][nt][0] = p; rs0 += p;
                p = rtf(ex2(s[u][nt][1] - mn0)); s[u][nt][1] = p; rs0 += p;
                p = rtf(ex2(s[u][nt][2] - mn1)); s[u][nt][2] = p; rs1 += p;
                p = rtf(ex2(s[u][nt][3] - mn1)); s[u][nt][3] = p; rs1 += p;
                o[u][nt][0] *= corr0; o[u][nt][1] *= corr0;
                o[u][nt][2] *= corr1; o[u][nt][3] *= corr1;
            }
            rs0 += __shfl_xor_sync(0xffffffffu, rs0, 1);
            rs0 += __shfl_xor_sync(0xffffffffu, rs0, 2);
            rs1 += __shfl_xor_sync(0xffffffffu, rs1, 1);
            rs1 += __shfl_xor_sync(0xffffffffu, rs1, 2);
            l[u][0] = l[u][0] * corr0 + rs0;
            l[u][1] = l[u][1] * corr1 + rs1;
        }

        // P -> per-warp smem (32 rows), then PV; V fragments shared across u
        #pragma unroll
        for (int u = 0; u < 2; u++) {
            #pragma unroll
            for (int nt = 0; nt < 8; nt++) {
                *(float2*)(Pw + (u * 16 + g) * PSTR + nt * 8 + 2 * t) =
                    make_float2(s[u][nt][0], s[u][nt][1]);
                *(float2*)(Pw + (u * 16 + g + 8) * PSTR + nt * 8 + 2 * t) =
                    make_float2(s[u][nt][2], s[u][nt][3]);
            }
        }
        __syncwarp();
        #pragma unroll
        for (int kc = 0; kc < 8; kc++) {
            unsigned pa[2][4];
            #pragma unroll
            for (int u = 0; u < 2; u++) {
                pa[u][0] = __float_as_uint(Pw[(u * 16 + g) * PSTR + kc * 8 + t]);
                pa[u][1] = __float_as_uint(Pw[(u * 16 + g + 8) * PSTR + kc * 8 + t]);
                pa[u][2] = __float_as_uint(Pw[(u * 16 + g) * PSTR + kc * 8 + t + 4]);
                pa[u][3] = __float_as_uint(Pw[(u * 16 + g + 8) * PSTR + kc * 8 + t + 4]);
            }
            #pragma unroll
            for (int nt = 0; nt < 8; nt++) {
                unsigned bf[2];
                bf[0] = __float_as_uint(Vs[(kc * 8 + t) * KVSTR + nt * 8 + g]);
                bf[1] = __float_as_uint(Vs[(kc * 8 + t + 4) * KVSTR + nt * 8 + g]);
                MMA_TF32(o[0][nt], pa[0], bf);
                MMA_TF32(o[1][nt], pa[1], bf);
            }
        }
        __syncwarp();   // P reused next tile
    }

    // epilogue: normalize, round, interleave -> g_ar (GEMM2's A operand)
    const int p0 = 2 * (2 * t & 3) + (t >> 1);
    const int p1 = 2 * ((2 * t + 1) & 3) + (t >> 1);
    #pragma unroll
    for (int u = 0; u < 2; u++) {
        const float inv0 = 1.f / l[u][0];
        const float inv1 = 1.f / l[u][1];
        float* op0 = outA + (size_t)b * SS * DD
                   + (size_t)(q0 + rb + u * 16 + g) * DD + h * HD;
        float* op1 = op0 + (size_t)8 * DD;
        #pragma unroll
        for (int nt = 0; nt < 8; nt++) {
            const int gb = nt * 8;
            op0[gb + p0] = rtf(o[u][nt][0] * inv0);
            op0[gb + p1] = rtf(o[u][nt][1] * inv0);
            op1[gb + p0] = rtf(o[u][nt][2] * inv1);
            op1[gb + p1] = rtf(o[u][nt][3] * inv1);
        }
    }
}

// ---------------------------------------------------------------------------
// Launch
// ---------------------------------------------------------------------------
extern "C" void kernel_launch(void* const* d_in, const int* in_sizes, int n_in,
                              void* d_out, int out_size)
{
    const float* x     = (const float*)d_in[0];
    const float* W_qkv = (const float*)d_in[1];
    const float* b_qkv = (const float*)d_in[2];
    const float* W_out = (const float*)d_in[3];
    const float* b_out = (const float*)d_in[4];
    float* out = (float*)d_out;

    float *qkv, *xr, *ar, *wqt, *wot;
    cudaGetSymbolAddress((void**)&qkv, g_qkv);
    cudaGetSymbolAddress((void**)&xr,  g_xr);
    cudaGetSymbolAddress((void**)&ar,  g_ar);
    cudaGetSymbolAddress((void**)&wqt, g_wqt);
    cudaGetSymbolAddress((void**)&wot, g_wot);

    cudaFuncSetAttribute(tgemm_tf32,
                         cudaFuncAttributeMaxDynamicSharedMemorySize, TG_SMEM);
    cudaFuncSetAttribute(attn_tc_kernel,
                         cudaFuncAttributeMaxDynamicSharedMemorySize, AT_SMEM);

    // 0) preprocess
    {
        int n4 = MM * DD / 4;
        round_perm<<<(n4 + 255) / 256, 256>>>((const float4*)x, xr, n4);
        dim3 tb(32, 8);
        wtrans_perm<<<dim3(D3 / 32, DD / 32), tb>>>(W_qkv, wqt, DD, D3);
        wtrans_perm<<<dim3(DD / 32, DD / 32), tb>>>(W_out, wot, DD, DD);
    }
    // 1) QKV projection (mode 1: rtf; interleave Q/K col regions)
    tgemm_tf32<<<dim3(D3 / TG_BN, MM / TG_BM), 256, TG_SMEM>>>(
        xr, wqt, b_qkv, qkv, D3, DD, 1);
    // 2) flash attention -> g_ar (rounded + interleaved)
    attn_tc_kernel<<<dim3(SS / 256, BB * HH), 256, AT_SMEM>>>(qkv, ar);
    // 3) output projection (mode 0: plain final output)
    tgemm_tf32<<<dim3(DD / TG_BN, MM / TG_BM), 256, TG_SMEM>>>(
        ar, wot, b_out, out, DD, DD, 0);
}

// round 11
// speedup vs baseline: 5.7262x; 1.0027x over previous
#include <cuda_runtime.h>
#include <math.h>
#include <stdint.h>

// Problem constants
#define BB 2
#define SS 2048
#define DD 1024
#define HH 16
#define HD 64
#define D3 (3 * DD)
#define MM (BB * SS)   // 4096

// ---------------------------------------------------------------------------
// Global scratch (no allocation allowed)
// ---------------------------------------------------------------------------
__device__ float g_qkv[MM * D3];   // [B,S,3D]; Q,K col-regions k-interleaved+tf32, V plain+tf32
__device__ float g_xr[MM * DD];    // x, tf32-rounded, k-interleaved
__device__ float g_ar[MM * DD];    // attn out, tf32-rounded, k-interleaved
__device__ float g_wqt[D3 * DD];   // W_qkv^T [N=3072][K=1024], rounded, k-interleaved
__device__ float g_wot[DD * DD];   // W_out^T [N=1024][K=1024], rounded, k-interleaved

// Interleave perm within 8-group: logical k -> position (k&3)*2 | (k>>2)
__device__ __forceinline__ int kperm(int k) {
    return (k & ~7) | (((k & 7) & 3) * 2) | (((k & 7) >> 2) & 1);
}

// ---------------------------------------------------------------------------
// Helpers
// ---------------------------------------------------------------------------
__device__ __forceinline__ float rtf(float x) {       // fp32 -> tf32 RN
    return __int_as_float(__float_as_int(x) + 0x1000);
}
__device__ __forceinline__ unsigned rtu(float x) {
    return (unsigned)(__float_as_int(x) + 0x1000);
}
__device__ __forceinline__ float ex2(float x) {       // MUFU exp2
    float r;
    asm("ex2.approx.f32 %0, %1;" : "=f"(r) : "f"(x));
    return r;
}
__device__ __forceinline__ uint32_t smem_u32(const void* p) {
    uint32_t a;
    asm("{ .reg .u64 t; cvta.to.shared.u64 t, %1; cvt.u32.u64 %0, t; }"
        : "=r"(a) : "l"(p));
    return a;
}
#define CP_ASYNC16(dst, src)                                                  \
    asm volatile("cp.async.cg.shared.global [%0], [%1], 16;"                  \
                 :: "r"(dst), "l"(src) : "memory")
#define CP_COMMIT() asm volatile("cp.async.commit_group;" ::: "memory")
#define CP_WAIT1()  asm volatile("cp.async.wait_group 1;" ::: "memory")

#define MMA_TF32(d, a, b)                                                     \
    asm volatile(                                                             \
        "mma.sync.aligned.m16n8k8.row.col.f32.tf32.tf32.f32 "                 \
        "{%0,%1,%2,%3}, {%4,%5,%6,%7}, {%8,%9}, {%0,%1,%2,%3};"               \
        : "+f"((d)[0]), "+f"((d)[1]), "+f"((d)[2]), "+f"((d)[3])              \
        : "r"((a)[0]), "r"((a)[1]), "r"((a)[2]), "r"((a)[3]),                 \
          "r"((b)[0]), "r"((b)[1]))

// ---------------------------------------------------------------------------
// Preprocess kernels (round to tf32 + k-interleave)
// ---------------------------------------------------------------------------
__global__ void round_perm(const float4* __restrict__ src,
                           float* __restrict__ dst, int n4)
{
    int i = blockIdx.x * blockDim.x + threadIdx.x;
    if (i >= n4) return;
    float4 v = src[i];
    const int e = i * 4;
    const int base = e & ~7;
    const int half = (e >> 2) & 1;
    float* d = dst + base + half;
    d[0] = rtf(v.x); d[2] = rtf(v.y); d[4] = rtf(v.z); d[6] = rtf(v.w);
}

// W [K][N] -> Wt [N][K] rounded + k-interleaved
__global__ void wtrans_perm(const float* __restrict__ W,
                            float* __restrict__ T, int K, int N)
{
    __shared__ float tile[32][33];
    const int k0 = blockIdx.y * 32, n0 = blockIdx.x * 32;
    const int tx = threadIdx.x, ty = threadIdx.y;   // 32 x 8
    #pragma unroll
    for (int i = 0; i < 32; i += 8)
        tile[ty + i][tx] = W[(size_t)(k0 + ty + i) * N + n0 + tx];
    __syncthreads();
    const int kk = kperm(k0 + tx);
    #pragma unroll
    for (int i = 0; i < 32; i += 8)
        T[(size_t)(n0 + ty + i) * K + kk] = rtf(tile[tx][ty + i]);
}

// ---------------------------------------------------------------------------
// TF32 GEMM v2: C[M,N] = A[M,K] @ Bt[N,K]^T + bias
// Block 128x128x32, 8 warps (2m x 4n), warp tile 64x32, 2-stage cp.async,
// 80KB smem -> 2 CTAs/SM (4 warps/SMSP for latency hiding).
// Per-element k-accumulation order identical to v1 -> bit-identical output.
// mode: 0 = plain output. 1 = qkv output: rtf; k-interleave if col<2048.
// ---------------------------------------------------------------------------
#define TG_BM 128
#define TG_BN 128
#define TG_BK 32
#define TSTR 40
#define SA_FLT (TG_BM * TSTR)            // 5120
#define SB_FLT (TG_BN * TSTR)            // 5120
#define STG_FLT (SA_FLT + SB_FLT)        // 10240
#define TG_SMEM (2 * STG_FLT * 4)        // 81920 bytes

__device__ __forceinline__ void g_stage(uint32_t sA, uint32_t sB,
                                        const float* __restrict__ A,
                                        const float* __restrict__ Bt,
                                        int bm0, int bn0, int kc, int K, int tid)
{
    #pragma unroll
    for (int it = 0; it < 4; it++) {
        const int u = tid + it * 256;
        const int row = u >> 3, seg = u & 7;
        CP_ASYNC16(sA + row * 160 + seg * 16,
                   A + (size_t)(bm0 + row) * K + kc + seg * 4);
    }
    #pragma unroll
    for (int it = 0; it < 4; it++) {
        const int u = tid + it * 256;
        const int row = u >> 3, seg = u & 7;
        CP_ASYNC16(sB + row * 160 + seg * 16,
                   Bt + (size_t)(bn0 + row) * K + kc + seg * 4);
    }
    CP_COMMIT();
}

__global__ void __launch_bounds__(256, 2)
tgemm_tf32(const float* __restrict__ A, const float* __restrict__ Bt,
           const float* __restrict__ bias, float* __restrict__ C,
           int N, int K, int mode)
{
    extern __shared__ float sm[];
    const uint32_t smb = smem_u32(sm);

    const int tid  = threadIdx.x;
    const int lane = tid & 31, wid = tid >> 5;
    const int g = lane >> 2, t = lane & 3;
    const int wm = wid & 1, wn = wid >> 1;          // 2 m-warps x 4 n-warps
    const int bm0 = blockIdx.y * TG_BM, bn0 = blockIdx.x * TG_BN;

    float c[4][4][4];
    #pragma unroll
    for (int mt = 0; mt < 4; mt++)
        #pragma unroll
        for (int nt = 0; nt < 4; nt++)
            #pragma unroll
            for (int r = 0; r < 4; r++) c[mt][nt][r] = 0.f;

    const int NC = K / TG_BK;    // 32
    g_stage(smb, smb + SA_FLT * 4, A, Bt, bm0, bn0, 0, K, tid);
    g_stage(smb + STG_FLT * 4, smb + (STG_FLT + SA_FLT) * 4,
            A, Bt, bm0, bn0, TG_BK, K, tid);

    for (int cix = 0; cix < NC; cix++) {
        CP_WAIT1();                 // chunk cix's group complete
        __syncthreads();            // all threads' copies visible

        const float* As_ = sm + (cix & 1) * STG_FLT;
        const float* Bs_ = As_ + SA_FLT;
        #pragma unroll
        for (int ks = 0; ks < 4; ks++) {
            const int kk = ks * 8;
            unsigned a[4][4], bf[4][2];
            #pragma unroll
            for (int mt = 0; mt < 4; mt++) {
                const int r0 = (wm * 64 + mt * 16 + g) * TSTR + kk + 2 * t;
                uint2 v0 = *(const uint2*)(As_ + r0);
                uint2 v1 = *(const uint2*)(As_ + r0 + 8 * TSTR);
                a[mt][0] = v0.x; a[mt][2] = v0.y;
                a[mt][1] = v1.x; a[mt][3] = v1.y;
            }
            #pragma unroll
            for (int nt = 0; nt < 4; nt++) {
                const int cb = (wn * 32 + nt * 8 + g) * TSTR + kk + 2 * t;
                uint2 v = *(const uint2*)(Bs_ + cb);
                bf[nt][0] = v.x; bf[nt][1] = v.y;
            }
            #pragma unroll
            for (int mt = 0; mt < 4; mt++)
                #pragma unroll
                for (int nt = 0; nt < 4; nt++)
                    MMA_TF32(c[mt][nt], a[mt], bf[nt]);
        }
        __syncthreads();            // WAR: buffer about to be restaged
        if (cix + 2 < NC)
            g_stage(smb + (cix & 1) * STG_FLT * 4,
                    smb + ((cix & 1) * STG_FLT + SA_FLT) * 4,
                    A, Bt, bm0, bn0, (cix + 2) * TG_BK, K, tid);
        else
            CP_COMMIT();            // keep wait-group accounting uniform
    }

    // epilogue
    const bool ilv = (mode == 1) && (bn0 < 2048);
    const int p0 = 2 * (2 * t & 3) + (t >> 1);
    const int p1 = 2 * ((2 * t + 1) & 3) + (t >> 1);
    #pragma unroll
    for (int mt = 0; mt < 4; mt++) {
        const int row = bm0 + wm * 64 + mt * 16 + g;
        #pragma unroll
        for (int nt = 0; nt < 4; nt++) {
            const int col = bn0 + wn * 32 + nt * 8 + 2 * t;
            float2 bv = *(const float2*)(bias + col);
            float v00 = c[mt][nt][0] + bv.x, v01 = c[mt][nt][1] + bv.y;
            float v10 = c[mt][nt][2] + bv.x, v11 = c[mt][nt][3] + bv.y;
            if (mode == 1) {
                v00 = rtf(v00); v01 = rtf(v01); v10 = rtf(v10); v11 = rtf(v11);
            }
            float* r0p = C + (size_t)row * N;
            float* r1p = C + (size_t)(row + 8) * N;
            if (ilv) {
                const int gb = bn0 + wn * 32 + nt * 8;
                r0p[gb + p0] = v00; r0p[gb + p1] = v01;
                r1p[gb + p0] = v10; r1p[gb + p1] = v11;
            } else {
                *(float2*)(r0p + col) = make_float2(v00, v01);
                *(float2*)(r1p + col) = make_float2(v10, v11);
            }
        }
    }
}

// ---------------------------------------------------------------------------
// TF32 flash attention (unchanged from round 8): 32 q-rows per warp,
// 8 warps, 256 query rows/block, 64-key tiles, cp.async double-buffered.
// grid (S/256, B*H), 256 threads.
// ---------------------------------------------------------------------------
#define KVSTR 72
#define PSTR  72
#define KV_FLT (64 * KVSTR)                      // 4608 floats per tile
#define AT_SMEM ((4 * KV_FLT + 8 * 32 * PSTR) * 4)   // 147456 B
#define QSCALE 0.18033688f                       // (1/sqrt(64)) * log2(e)

__device__ __forceinline__ void a_stage(uint32_t kb, uint32_t vb,
                                        const float* __restrict__ base,
                                        int kt, int h, int tid)
{
    const float* kg = base + DD + h * HD;
    const float* vg = base + 2 * DD + h * HD;
    #pragma unroll
    for (int it = 0; it < 4; it++) {
        const int u = tid + it * 256;
        const int row = u >> 4, cseg = u & 15;
        CP_ASYNC16(kb + row * 288 + cseg * 16,
                   kg + (size_t)(kt + row) * D3 + cseg * 4);
    }
    #pragma unroll
    for (int it = 0; it < 4; it++) {
        const int u = tid + it * 256;
        const int row = u >> 4, cseg = u & 15;
        CP_ASYNC16(vb + row * 288 + cseg * 16,
                   vg + (size_t)(kt + row) * D3 + cseg * 4);
    }
    CP_COMMIT();
}

__global__ void __launch_bounds__(256, 1)
attn_tc_kernel(const float* __restrict__ qkv, float* __restrict__ outA)
{
    extern __shared__ float sm[];
    const uint32_t smb = smem_u32(sm);
    float* Ksb[2] = { sm,          sm + 2 * KV_FLT };
    float* Vsb[2] = { sm + KV_FLT, sm + 3 * KV_FLT };
    const uint32_t kaddr[2] = { smb, smb + 2 * KV_FLT * 4 };
    const uint32_t vaddr[2] = { smb + KV_FLT * 4, smb + 3 * KV_FLT * 4 };

    const int tid  = threadIdx.x;
    const int lane = tid & 31, wid = tid >> 5;
    const int g = lane >> 2, t = lane & 3;
    const int bh = blockIdx.y, b = bh >> 4, h = bh & 15;
    const int q0 = blockIdx.x * 256;
    const int rb = wid * 32;                    // warp's 32-row base

    float* Pw = sm + 4 * KV_FLT + wid * 32 * PSTR;

    const float* base = qkv + (size_t)b * SS * D3;

    a_stage(kaddr[0], vaddr[0], base, 0, h, tid);

    // Q fragments: 2 row-groups x 8 k-chunks (gmem tf32-rounded + interleaved)
    unsigned qa[2][8][4];
    {
        const float* qp = base + (size_t)q0 * D3 + h * HD;
        #pragma unroll
        for (int u = 0; u < 2; u++) {
            const int r0 = rb + u * 16 + g;
            #pragma unroll
            for (int kc = 0; kc < 8; kc++) {
                float2 v0 = *(const float2*)(qp + (size_t)r0 * D3 + kc * 8 + 2 * t);
                float2 v1 = *(const float2*)(qp + (size_t)(r0 + 8) * D3 + kc * 8 + 2 * t);
                qa[u][kc][0] = rtu(v0.x * QSCALE); qa[u][kc][2] = rtu(v0.y * QSCALE);
                qa[u][kc][1] = rtu(v1.x * QSCALE); qa[u][kc][3] = rtu(v1.y * QSCALE);
            }
        }
    }

    float o[2][8][4];
    #pragma unroll
    for (int u = 0; u < 2; u++)
        #pragma unroll
        for (int nt = 0; nt < 8; nt++)
            #pragma unroll
            for (int r = 0; r < 4; r++) o[u][nt][r] = 0.f;
    float m[2][2] = { { -1e30f, -1e30f }, { -1e30f, -1e30f } };
    float l[2][2] = { { 0.f, 0.f }, { 0.f, 0.f } };

    const int NT = SS / 64;   // 32
    for (int i = 0; i < NT; i++) {
        const int buf = i & 1;
        __syncthreads();                      // WAR: prev consume of buf^1 done
        if (i + 1 < NT)
            a_stage(kaddr[buf ^ 1], vaddr[buf ^ 1], base, (i + 1) * 64, h, tid);
        else
            CP_COMMIT();
        CP_WAIT1();
        __syncthreads();                      // RAW: all copies of buf visible

        const float* Ks = Ksb[buf];
        const float* Vs = Vsb[buf];

        // S = Q K^T : K fragments shared across both row-groups
        float s[2][8][4];
        #pragma unroll
        for (int u = 0; u < 2; u++)
            #pragma unroll
            for (int nt = 0; nt < 8; nt++)
                #pragma unroll
                for (int r = 0; r < 4; r++) s[u][nt][r] = 0.f;
        #pragma unroll
        for (int kc = 0; kc < 8; kc++) {
            #pragma unroll
            for (int nt = 0; nt < 8; nt++) {
                uint2 kv = *(const uint2*)(Ks + (nt * 8 + g) * KVSTR + kc * 8 + 2 * t);
                unsigned bf[2] = { kv.x, kv.y };
                MMA_TF32(s[0][nt], qa[0][kc], bf);
                MMA_TF32(s[1][nt], qa[1][kc], bf);
            }
        }

        // online softmax per row-group (base-2 domain)
        #pragma unroll
        for (int u = 0; u < 2; u++) {
            float cm0 = s[u][0][0], cm1 = s[u][0][2];
            #pragma unroll
            for (int nt = 0; nt < 8; nt++) {
                cm0 = fmaxf(cm0, fmaxf(s[u][nt][0], s[u][nt][1]));
                cm1 = fmaxf(cm1, fmaxf(s[u][nt][2], s[u][nt][3]));
            }
            cm0 = fmaxf(cm0, __shfl_xor_sync(0xffffffffu, cm0, 1));
            cm0 = fmaxf(cm0, __shfl_xor_sync(0xffffffffu, cm0, 2));
            cm1 = fmaxf(cm1, __shfl_xor_sync(0xffffffffu, cm1, 1));
            cm1 = fmaxf(cm1, __shfl_xor_sync(0xffffffffu, cm1, 2));
            const float mn0 = fmaxf(m[u][0], cm0);
            const float mn1 = fmaxf(m[u][1], cm1);
            const float corr0 = ex2(m[u][0] - mn0);
            const float corr1 = ex2(m[u][1] - mn1);
            m[u][0] = mn0; m[u][1] = mn1;

            float rs0 = 0.f, rs1 = 0.f;
            #pragma unroll
            for (int nt = 0; nt < 8; nt++) {
                float p;
                p = rtf(ex2(s[u][nt][0] - mn0)); s[u][nt][0] = p; rs0 += p;
                p = rtf(ex2(s[u][nt][1] - mn0)); s[u][nt][1] = p; rs0 += p;
                p = rtf(ex2(s[u][nt][2] - mn1)); s[u][nt][2] = p; rs1 += p;
                p = rtf(ex2(s[u][nt][3] - mn1)); s[u][nt][3] = p; rs1 += p;
                o[u][nt][0] *= corr0; o[u][nt][1] *= corr0;
                o[u][nt][2] *= corr1; o[u][nt][3] *= corr1;
            }
            rs0 += __shfl_xor_sync(0xffffffffu, rs0, 1);
            rs0 += __shfl_xor_sync(0xffffffffu, rs0, 2);
            rs1 += __shfl_xor_sync(0xffffffffu, rs1, 1);
            rs1 += __shfl_xor_sync(0xffffffffu, rs1, 2);
            l[u][0] = l[u][0] * corr0 + rs0;
            l[u][1] = l[u][1] * corr1 + rs1;
        }

        // P -> per-warp smem (32 rows), then PV; V fragments shared across u
        #pragma unroll
        for (int u = 0; u < 2; u++) {
            #pragma unroll
            for (int nt = 0; nt < 8; nt++) {
                *(float2*)(Pw + (u * 16 + g) * PSTR + nt * 8 + 2 * t) =
                    make_float2(s[u][nt][0], s[u][nt][1]);
                *(float2*)(Pw + (u * 16 + g + 8) * PSTR + nt * 8 + 2 * t) =
                    make_float2(s[u][nt][2], s[u][nt][3]);
            }
        }
        __syncwarp();
        #pragma unroll
        for (int kc = 0; kc < 8; kc++) {
            unsigned pa[2][4];
            #pragma unroll
            for (int u = 0; u < 2; u++) {
                pa[u][0] = __float_as_uint(Pw[(u * 16 + g) * PSTR + kc * 8 + t]);
                pa[u][1] = __float_as_uint(Pw[(u * 16 + g + 8) * PSTR + kc * 8 + t]);
                pa[u][2] = __float_as_uint(Pw[(u * 16 + g) * PSTR + kc * 8 + t + 4]);
                pa[u][3] = __float_as_uint(Pw[(u * 16 + g + 8) * PSTR + kc * 8 + t + 4]);
            }
            #pragma unroll
            for (int nt = 0; nt < 8; nt++) {
                unsigned bf[2];
                bf[0] = __float_as_uint(Vs[(kc * 8 + t) * KVSTR + nt * 8 + g]);
                bf[1] = __float_as_uint(Vs[(kc * 8 + t + 4) * KVSTR + nt * 8 + g]);
                MMA_TF32(o[0][nt], pa[0], bf);
                MMA_TF32(o[1][nt], pa[1], bf);
            }
        }
        __syncwarp();   // P reused next tile
    }

    // epilogue: normalize, round, interleave -> g_ar (GEMM2's A operand)
    const int p0 = 2 * (2 * t & 3) + (t >> 1);
    const int p1 = 2 * ((2 * t + 1) & 3) + (t >> 1);
    #pragma unroll
    for (int u = 0; u < 2; u++) {
        const float inv0 = 1.f / l[u][0];
        const float inv1 = 1.f / l[u][1];
        float* op0 = outA + (size_t)b * SS * DD
                   + (size_t)(q0 + rb + u * 16 + g) * DD + h * HD;
        float* op1 = op0 + (size_t)8 * DD;
        #pragma unroll
        for (int nt = 0; nt < 8; nt++) {
            const int gb = nt * 8;
            op0[gb + p0] = rtf(o[u][nt][0] * inv0);
            op0[gb + p1] = rtf(o[u][nt][1] * inv0);
            op1[gb + p0] = rtf(o[u][nt][2] * inv1);
            op1[gb + p1] = rtf(o[u][nt][3] * inv1);
        }
    }
}

// ---------------------------------------------------------------------------
// Launch
// ---------------------------------------------------------------------------
extern "C" void kernel_launch(void* const* d_in, const int* in_sizes, int n_in,
                              void* d_out, int out_size)
{
    const float* x     = (const float*)d_in[0];
    const float* W_qkv = (const float*)d_in[1];
    const float* b_qkv = (const float*)d_in[2];
    const float* W_out = (const float*)d_in[3];
    const float* b_out = (const float*)d_in[4];
    float* out = (float*)d_out;

    float *qkv, *xr, *ar, *wqt, *wot;
    cudaGetSymbolAddress((void**)&qkv, g_qkv);
    cudaGetSymbolAddress((void**)&xr,  g_xr);
    cudaGetSymbolAddress((void**)&ar,  g_ar);
    cudaGetSymbolAddress((void**)&wqt, g_wqt);
    cudaGetSymbolAddress((void**)&wot, g_wot);

    cudaFuncSetAttribute(tgemm_tf32,
                         cudaFuncAttributeMaxDynamicSharedMemorySize, TG_SMEM);
    cudaFuncSetAttribute(attn_tc_kernel,
                         cudaFuncAttributeMaxDynamicSharedMemorySize, AT_SMEM);

    // 0) preprocess
    {
        int n4 = MM * DD / 4;
        round_perm<<<(n4 + 255) / 256, 256>>>((const float4*)x, xr, n4);
        dim3 tb(32, 8);
        wtrans_perm<<<dim3(D3 / 32, DD / 32), tb>>>(W_qkv, wqt, DD, D3);
        wtrans_perm<<<dim3(DD / 32, DD / 32), tb>>>(W_out, wot, DD, DD);
    }
    // 1) QKV projection (mode 1: rtf; interleave Q/K col regions)
    tgemm_tf32<<<dim3(D3 / TG_BN, MM / TG_BM), 256, TG_SMEM>>>(
        xr, wqt, b_qkv, qkv, D3, DD, 1);
    // 2) flash attention -> g_ar (rounded + interleaved)
    attn_tc_kernel<<<dim3(SS / 256, BB * HH), 256, AT_SMEM>>>(qkv, ar);
    // 3) output projection (mode 0: plain final output)
    tgemm_tf32<<<dim3(DD / TG_BN, MM / TG_BM), 256, TG_SMEM>>>(
        ar, wot, b_out, out, DD, DD, 0);
}

// round 13
// speedup vs baseline: 5.9523x; 1.0395x over previous
#include <cuda_runtime.h>
#include <math.h>
#include <stdint.h>

// Problem constants
#define BB 2
#define SS 2048
#define DD 1024
#define HH 16
#define HD 64
#define D3 (3 * DD)
#define MM (BB * SS)   // 4096

// ---------------------------------------------------------------------------
// Global scratch (no allocation allowed)
// ---------------------------------------------------------------------------
__device__ float g_qkv[MM * D3];   // [B,S,3D]; Q,K col-regions k-interleaved+tf32, V plain+tf32
__device__ float g_xr[MM * DD];    // x, tf32-rounded, k-interleaved
__device__ float g_ar[MM * DD];    // attn out, tf32-rounded, k-interleaved
__device__ float g_wqt[D3 * DD];   // W_qkv^T [N=3072][K=1024], rounded, k-interleaved
__device__ float g_wot[DD * DD];   // W_out^T [N=1024][K=1024], rounded, k-interleaved

// Interleave perm within 8-group: logical k -> position (k&3)*2 | (k>>2)
__device__ __forceinline__ int kperm(int k) {
    return (k & ~7) | (((k & 7) & 3) * 2) | (((k & 7) >> 2) & 1);
}

// ---------------------------------------------------------------------------
// Helpers
// ---------------------------------------------------------------------------
__device__ __forceinline__ float rtf(float x) {       // fp32 -> tf32 RN
    return __int_as_float(__float_as_int(x) + 0x1000);
}
__device__ __forceinline__ unsigned rtu(float x) {
    return (unsigned)(__float_as_int(x) + 0x1000);
}
__device__ __forceinline__ float ex2(float x) {       // MUFU exp2
    float r;
    asm("ex2.approx.f32 %0, %1;" : "=f"(r) : "f"(x));
    return r;
}
__device__ __forceinline__ uint32_t smem_u32(const void* p) {
    uint32_t a;
    asm("{ .reg .u64 t; cvta.to.shared.u64 t, %1; cvt.u32.u64 %0, t; }"
        : "=r"(a) : "l"(p));
    return a;
}
#define CP_ASYNC16(dst, src)                                                  \
    asm volatile("cp.async.cg.shared.global [%0], [%1], 16;"                  \
                 :: "r"(dst), "l"(src) : "memory")
#define CP_COMMIT() asm volatile("cp.async.commit_group;" ::: "memory")
#define CP_WAIT1()  asm volatile("cp.async.wait_group 1;" ::: "memory")

#define MMA_TF32(d, a, b)                                                     \
    asm volatile(                                                             \
        "mma.sync.aligned.m16n8k8.row.col.f32.tf32.tf32.f32 "                 \
        "{%0,%1,%2,%3}, {%4,%5,%6,%7}, {%8,%9}, {%0,%1,%2,%3};"               \
        : "+f"((d)[0]), "+f"((d)[1]), "+f"((d)[2]), "+f"((d)[3])              \
        : "r"((a)[0]), "r"((a)[1]), "r"((a)[2]), "r"((a)[3]),                 \
          "r"((b)[0]), "r"((b)[1]))

// ---------------------------------------------------------------------------
// Preprocess kernels (round to tf32 + k-interleave)
// ---------------------------------------------------------------------------
__global__ void round_perm(const float4* __restrict__ src,
                           float* __restrict__ dst, int n4)
{
    int i = blockIdx.x * blockDim.x + threadIdx.x;
    if (i >= n4) return;
    float4 v = src[i];
    const int e = i * 4;
    const int base = e & ~7;
    const int half = (e >> 2) & 1;
    float* d = dst + base + half;
    d[0] = rtf(v.x); d[2] = rtf(v.y); d[4] = rtf(v.z); d[6] = rtf(v.w);
}

// W [K][N] -> Wt [N][K] rounded + k-interleaved
__global__ void wtrans_perm(const float* __restrict__ W,
                            float* __restrict__ T, int K, int N)
{
    __shared__ float tile[32][33];
    const int k0 = blockIdx.y * 32, n0 = blockIdx.x * 32;
    const int tx = threadIdx.x, ty = threadIdx.y;   // 32 x 8
    #pragma unroll
    for (int i = 0; i < 32; i += 8)
        tile[ty + i][tx] = W[(size_t)(k0 + ty + i) * N + n0 + tx];
    __syncthreads();
    const int kk = kperm(k0 + tx);
    #pragma unroll
    for (int i = 0; i < 32; i += 8)
        T[(size_t)(n0 + ty + i) * K + kk] = rtf(tile[tx][ty + i]);
}

// ---------------------------------------------------------------------------
// TF32 GEMM v2 (unchanged from round 11): C[M,N] = A[M,K] @ Bt[N,K]^T + bias
// ---------------------------------------------------------------------------
#define TG_BM 128
#define TG_BN 128
#define TG_BK 32
#define TSTR 40
#define SA_FLT (TG_BM * TSTR)            // 5120
#define SB_FLT (TG_BN * TSTR)            // 5120
#define STG_FLT (SA_FLT + SB_FLT)        // 10240
#define TG_SMEM (2 * STG_FLT * 4)        // 81920 bytes

__device__ __forceinline__ void g_stage(uint32_t sA, uint32_t sB,
                                        const float* __restrict__ A,
                                        const float* __restrict__ Bt,
                                        int bm0, int bn0, int kc, int K, int tid)
{
    #pragma unroll
    for (int it = 0; it < 4; it++) {
        const int u = tid + it * 256;
        const int row = u >> 3, seg = u & 7;
        CP_ASYNC16(sA + row * 160 + seg * 16,
                   A + (size_t)(bm0 + row) * K + kc + seg * 4);
    }
    #pragma unroll
    for (int it = 0; it < 4; it++) {
        const int u = tid + it * 256;
        const int row = u >> 3, seg = u & 7;
        CP_ASYNC16(sB + row * 160 + seg * 16,
                   Bt + (size_t)(bn0 + row) * K + kc + seg * 4);
    }
    CP_COMMIT();
}

__global__ void __launch_bounds__(256, 2)
tgemm_tf32(const float* __restrict__ A, const float* __restrict__ Bt,
           const float* __restrict__ bias, float* __restrict__ C,
           int N, int K, int mode)
{
    extern __shared__ float sm[];
    const uint32_t smb = smem_u32(sm);

    const int tid  = threadIdx.x;
    const int lane = tid & 31, wid = tid >> 5;
    const int g = lane >> 2, t = lane & 3;
    const int wm = wid & 1, wn = wid >> 1;          // 2 m-warps x 4 n-warps
    const int bm0 = blockIdx.y * TG_BM, bn0 = blockIdx.x * TG_BN;

    float c[4][4][4];
    #pragma unroll
    for (int mt = 0; mt < 4; mt++)
        #pragma unroll
        for (int nt = 0; nt < 4; nt++)
            #pragma unroll
            for (int r = 0; r < 4; r++) c[mt][nt][r] = 0.f;

    const int NC = K / TG_BK;    // 32
    g_stage(smb, smb + SA_FLT * 4, A, Bt, bm0, bn0, 0, K, tid);
    g_stage(smb + STG_FLT * 4, smb + (STG_FLT + SA_FLT) * 4,
            A, Bt, bm0, bn0, TG_BK, K, tid);

    for (int cix = 0; cix < NC; cix++) {
        CP_WAIT1();                 // chunk cix's group complete
        __syncthreads();            // all threads' copies visible

        const float* As_ = sm + (cix & 1) * STG_FLT;
        const float* Bs_ = As_ + SA_FLT;
        #pragma unroll
        for (int ks = 0; ks < 4; ks++) {
            const int kk = ks * 8;
            unsigned a[4][4], bf[4][2];
            #pragma unroll
            for (int mt = 0; mt < 4; mt++) {
                const int r0 = (wm * 64 + mt * 16 + g) * TSTR + kk + 2 * t;
                uint2 v0 = *(const uint2*)(As_ + r0);
                uint2 v1 = *(const uint2*)(As_ + r0 + 8 * TSTR);
                a[mt][0] = v0.x; a[mt][2] = v0.y;
                a[mt][1] = v1.x; a[mt][3] = v1.y;
            }
            #pragma unroll
            for (int nt = 0; nt < 4; nt++) {
                const int cb = (wn * 32 + nt * 8 + g) * TSTR + kk + 2 * t;
                uint2 v = *(const uint2*)(Bs_ + cb);
                bf[nt][0] = v.x; bf[nt][1] = v.y;
            }
            #pragma unroll
            for (int mt = 0; mt < 4; mt++)
                #pragma unroll
                for (int nt = 0; nt < 4; nt++)
                    MMA_TF32(c[mt][nt], a[mt], bf[nt]);
        }
        __syncthreads();            // WAR: buffer about to be restaged
        if (cix + 2 < NC)
            g_stage(smb + (cix & 1) * STG_FLT * 4,
                    smb + ((cix & 1) * STG_FLT + SA_FLT) * 4,
                    A, Bt, bm0, bn0, (cix + 2) * TG_BK, K, tid);
        else
            CP_COMMIT();            // keep wait-group accounting uniform
    }

    // epilogue
    const bool ilv = (mode == 1) && (bn0 < 2048);
    const int p0 = 2 * (2 * t & 3) + (t >> 1);
    const int p1 = 2 * ((2 * t + 1) & 3) + (t >> 1);
    #pragma unroll
    for (int mt = 0; mt < 4; mt++) {
        const int row = bm0 + wm * 64 + mt * 16 + g;
        #pragma unroll
        for (int nt = 0; nt < 4; nt++) {
            const int col = bn0 + wn * 32 + nt * 8 + 2 * t;
            float2 bv = *(const float2*)(bias + col);
            float v00 = c[mt][nt][0] + bv.x, v01 = c[mt][nt][1] + bv.y;
            float v10 = c[mt][nt][2] + bv.x, v11 = c[mt][nt][3] + bv.y;
            if (mode == 1) {
                v00 = rtf(v00); v01 = rtf(v01); v10 = rtf(v10); v11 = rtf(v11);
            }
            float* r0p = C + (size_t)row * N;
            float* r1p = C + (size_t)(row + 8) * N;
            if (ilv) {
                const int gb = bn0 + wn * 32 + nt * 8;
                r0p[gb + p0] = v00; r0p[gb + p1] = v01;
                r1p[gb + p0] = v10; r1p[gb + p1] = v11;
            } else {
                *(float2*)(r0p + col) = make_float2(v00, v01);
                *(float2*)(r1p + col) = make_float2(v10, v11);
            }
        }
    }
}

// ---------------------------------------------------------------------------
// TF32 flash attention v2: 4 warps per CTA, 32 q-rows/warp, q-tile 128,
// 110.6 KB smem -> 2 CTAs/SM. Two independent CTAs per SM interleave their
// MMA and softmax phases, filling the tensor pipe during non-MMA work.
// Per-row arithmetic order identical to round 8 -> bit-identical output.
// grid (S/128, B*H), 128 threads.
// ---------------------------------------------------------------------------
#define KVSTR 72
#define PSTR  72
#define KV_FLT (64 * KVSTR)                      // 4608 floats per tile
#define AT_SMEM ((4 * KV_FLT + 4 * 32 * PSTR) * 4)   // 110592 B
#define QSCALE 0.18033688f                       // (1/sqrt(64)) * log2(e)

__device__ __forceinline__ void a_stage(uint32_t kb, uint32_t vb,
                                        const float* __restrict__ base,
                                        int kt, int h, int tid)
{
    const float* kg = base + DD + h * HD;
    const float* vg = base + 2 * DD + h * HD;
    #pragma unroll
    for (int it = 0; it < 8; it++) {
        const int u = tid + it * 128;
        const int row = u >> 4, cseg = u & 15;
        CP_ASYNC16(kb + row * 288 + cseg * 16,
                   kg + (size_t)(kt + row) * D3 + cseg * 4);
    }
    #pragma unroll
    for (int it = 0; it < 8; it++) {
        const int u = tid + it * 128;
        const int row = u >> 4, cseg = u & 15;
        CP_ASYNC16(vb + row * 288 + cseg * 16,
                   vg + (size_t)(kt + row) * D3 + cseg * 4);
    }
    CP_COMMIT();
}

__global__ void __launch_bounds__(128, 2)
attn_tc_kernel(const float* __restrict__ qkv, float* __restrict__ outA)
{
    extern __shared__ float sm[];
    const uint32_t smb = smem_u32(sm);
    float* Ksb[2] = { sm,          sm + 2 * KV_FLT };
    float* Vsb[2] = { sm + KV_FLT, sm + 3 * KV_FLT };
    const uint32_t kaddr[2] = { smb, smb + 2 * KV_FLT * 4 };
    const uint32_t vaddr[2] = { smb + KV_FLT * 4, smb + 3 * KV_FLT * 4 };

    const int tid  = threadIdx.x;
    const int lane = tid & 31, wid = tid >> 5;       // wid 0..3
    const int g = lane >> 2, t = lane & 3;
    const int bh = blockIdx.y, b = bh >> 4, h = bh & 15;
    const int q0 = blockIdx.x * 128;
    const int rb = wid * 32;                          // warp's 32-row base

    float* Pw = sm + 4 * KV_FLT + wid * 32 * PSTR;

    const float* base = qkv + (size_t)b * SS * D3;

    a_stage(kaddr[0], vaddr[0], base, 0, h, tid);

    // Q fragments: 2 row-groups x 8 k-chunks (gmem tf32-rounded + interleaved)
    unsigned qa[2][8][4];
    {
        const float* qp = base + (size_t)q0 * D3 + h * HD;
        #pragma unroll
        for (int u = 0; u < 2; u++) {
            const int r0 = rb + u * 16 + g;
            #pragma unroll
            for (int kc = 0; kc < 8; kc++) {
                float2 v0 = *(const float2*)(qp + (size_t)r0 * D3 + kc * 8 + 2 * t);
                float2 v1 = *(const float2*)(qp + (size_t)(r0 + 8) * D3 + kc * 8 + 2 * t);
                qa[u][kc][0] = rtu(v0.x * QSCALE); qa[u][kc][2] = rtu(v0.y * QSCALE);
                qa[u][kc][1] = rtu(v1.x * QSCALE); qa[u][kc][3] = rtu(v1.y * QSCALE);
            }
        }
    }

    float o[2][8][4];
    #pragma unroll
    for (int u = 0; u < 2; u++)
        #pragma unroll
        for (int nt = 0; nt < 8; nt++)
            #pragma unroll
            for (int r = 0; r < 4; r++) o[u][nt][r] = 0.f;
    float m[2][2] = { { -1e30f, -1e30f }, { -1e30f, -1e30f } };
    float l[2][2] = { { 0.f, 0.f }, { 0.f, 0.f } };

    const int NT = SS / 64;   // 32
    for (int i = 0; i < NT; i++) {
        const int buf = i & 1;
        __syncthreads();                      // WAR: prev consume of buf^1 done
        if (i + 1 < NT)
            a_stage(kaddr[buf ^ 1], vaddr[buf ^ 1], base, (i + 1) * 64, h, tid);
        else
            CP_COMMIT();
        CP_WAIT1();
        __syncthreads();                      // RAW: all copies of buf visible

        const float* Ks = Ksb[buf];
        const float* Vs = Vsb[buf];

        // S = Q K^T : K fragments shared across both row-groups
        float s[2][8][4];
        #pragma unroll
        for (int u = 0; u < 2; u++)
            #pragma unroll
            for (int nt = 0; nt < 8; nt++)
                #pragma unroll
                for (int r = 0; r < 4; r++) s[u][nt][r] = 0.f;
        #pragma unroll
        for (int kc = 0; kc < 8; kc++) {
            #pragma unroll
            for (int nt = 0; nt < 8; nt++) {
                uint2 kv = *(const uint2*)(Ks + (nt * 8 + g) * KVSTR + kc * 8 + 2 * t);
                unsigned bf[2] = { kv.x, kv.y };
                MMA_TF32(s[0][nt], qa[0][kc], bf);
                MMA_TF32(s[1][nt], qa[1][kc], bf);
            }
        }

        // online softmax per row-group (base-2 domain)
        #pragma unroll
        for (int u = 0; u < 2; u++) {
            float cm0 = s[u][0][0], cm1 = s[u][0][2];
            #pragma unroll
            for (int nt = 0; nt < 8; nt++) {
                cm0 = fmaxf(cm0, fmaxf(s[u][nt][0], s[u][nt][1]));
                cm1 = fmaxf(cm1, fmaxf(s[u][nt][2], s[u][nt][3]));
            }
            cm0 = fmaxf(cm0, __shfl_xor_sync(0xffffffffu, cm0, 1));
            cm0 = fmaxf(cm0, __shfl_xor_sync(0xffffffffu, cm0, 2));
            cm1 = fmaxf(cm1, __shfl_xor_sync(0xffffffffu, cm1, 1));
            cm1 = fmaxf(cm1, __shfl_xor_sync(0xffffffffu, cm1, 2));
            const float mn0 = fmaxf(m[u][0], cm0);
            const float mn1 = fmaxf(m[u][1], cm1);
            const float corr0 = ex2(m[u][0] - mn0);
            const float corr1 = ex2(m[u][1] - mn1);
            m[u][0] = mn0; m[u][1] = mn1;

            float rs0 = 0.f, rs1 = 0.f;
            #pragma unroll
            for (int nt = 0; nt < 8; nt++) {
                float p;
                p = rtf(ex2(s[u][nt][0] - mn0)); s[u][nt][0] = p; rs0 += p;
                p = rtf(ex2(s[u][nt][1] - mn0)); s[u][nt][1] = p; rs0 += p;
                p = rtf(ex2(s[u][nt][2] - mn1)); s[u][nt][2] = p; rs1 += p;
                p = rtf(ex2(s[u][nt][3] - mn1)); s[u][nt][3] = p; rs1 += p;
                o[u][nt][0] *= corr0; o[u][nt][1] *= corr0;
                o[u][nt][2] *= corr1; o[u][nt][3] *= corr1;
            }
            rs0 += __shfl_xor_sync(0xffffffffu, rs0, 1);
            rs0 += __shfl_xor_sync(0xffffffffu, rs0, 2);
            rs1 += __shfl_xor_sync(0xffffffffu, rs1, 1);
            rs1 += __shfl_xor_sync(0xffffffffu, rs1, 2);
            l[u][0] = l[u][0] * corr0 + rs0;
            l[u][1] = l[u][1] * corr1 + rs1;
        }

        // P -> per-warp smem (32 rows), then PV; V fragments shared across u
        #pragma unroll
        for (int u = 0; u < 2; u++) {
            #pragma unroll
            for (int nt = 0; nt < 8; nt++) {
                *(float2*)(Pw + (u * 16 + g) * PSTR + nt * 8 + 2 * t) =
                    make_float2(s[u][nt][0], s[u][nt][1]);
                *(float2*)(Pw + (u * 16 + g + 8) * PSTR + nt * 8 + 2 * t) =
                    make_float2(s[u][nt][2], s[u][nt][3]);
            }
        }
        __syncwarp();
        #pragma unroll
        for (int kc = 0; kc < 8; kc++) {
            unsigned pa[2][4];
            #pragma unroll
            for (int u = 0; u < 2; u++) {
                pa[u][0] = __float_as_uint(Pw[(u * 16 + g) * PSTR + kc * 8 + t]);
                pa[u][1] = __float_as_uint(Pw[(u * 16 + g + 8) * PSTR + kc * 8 + t]);
                pa[u][2] = __float_as_uint(Pw[(u * 16 + g) * PSTR + kc * 8 + t + 4]);
                pa[u][3] = __float_as_uint(Pw[(u * 16 + g + 8) * PSTR + kc * 8 + t + 4]);
            }
            #pragma unroll
            for (int nt = 0; nt < 8; nt++) {
                unsigned bf[2];
                bf[0] = __float_as_uint(Vs[(kc * 8 + t) * KVSTR + nt * 8 + g]);
                bf[1] = __float_as_uint(Vs[(kc * 8 + t + 4) * KVSTR + nt * 8 + g]);
                MMA_TF32(o[0][nt], pa[0], bf);
                MMA_TF32(o[1][nt], pa[1], bf);
            }
        }
        __syncwarp();   // P reused next tile
    }

    // epilogue: normalize, round, interleave -> g_ar (GEMM2's A operand)
    const int p0 = 2 * (2 * t & 3) + (t >> 1);
    const int p1 = 2 * ((2 * t + 1) & 3) + (t >> 1);
    #pragma unroll
    for (int u = 0; u < 2; u++) {
        const float inv0 = 1.f / l[u][0];
        const float inv1 = 1.f / l[u][1];
        float* op0 = outA + (size_t)b * SS * DD
                   + (size_t)(q0 + rb + u * 16 + g) * DD + h * HD;
        float* op1 = op0 + (size_t)8 * DD;
        #pragma unroll
        for (int nt = 0; nt < 8; nt++) {
            const int gb = nt * 8;
            op0[gb + p0] = rtf(o[u][nt][0] * inv0);
            op0[gb + p1] = rtf(o[u][nt][1] * inv0);
            op1[gb + p0] = rtf(o[u][nt][2] * inv1);
            op1[gb + p1] = rtf(o[u][nt][3] * inv1);
        }
    }
}

// ---------------------------------------------------------------------------
// Launch
// ---------------------------------------------------------------------------
extern "C" void kernel_launch(void* const* d_in, const int* in_sizes, int n_in,
                              void* d_out, int out_size)
{
    const float* x     = (const float*)d_in[0];
    const float* W_qkv = (const float*)d_in[1];
    const float* b_qkv = (const float*)d_in[2];
    const float* W_out = (const float*)d_in[3];
    const float* b_out = (const float*)d_in[4];
    float* out = (float*)d_out;

    float *qkv, *xr, *ar, *wqt, *wot;
    cudaGetSymbolAddress((void**)&qkv, g_qkv);
    cudaGetSymbolAddress((void**)&xr,  g_xr);
    cudaGetSymbolAddress((void**)&ar,  g_ar);
    cudaGetSymbolAddress((void**)&wqt, g_wqt);
    cudaGetSymbolAddress((void**)&wot, g_wot);

    cudaFuncSetAttribute(tgemm_tf32,
                         cudaFuncAttributeMaxDynamicSharedMemorySize, TG_SMEM);
    cudaFuncSetAttribute(attn_tc_kernel,
                         cudaFuncAttributeMaxDynamicSharedMemorySize, AT_SMEM);

    // 0) preprocess
    {
        int n4 = MM * DD / 4;
        round_perm<<<(n4 + 255) / 256, 256>>>((const float4*)x, xr, n4);
        dim3 tb(32, 8);
        wtrans_perm<<<dim3(D3 / 32, DD / 32), tb>>>(W_qkv, wqt, DD, D3);
        wtrans_perm<<<dim3(DD / 32, DD / 32), tb>>>(W_out, wot, DD, DD);
    }
    // 1) QKV projection (mode 1: rtf; interleave Q/K col regions)
    tgemm_tf32<<<dim3(D3 / TG_BN, MM / TG_BM), 256, TG_SMEM>>>(
        xr, wqt, b_qkv, qkv, D3, DD, 1);
    // 2) flash attention -> g_ar (rounded + interleaved)
    attn_tc_kernel<<<dim3(SS / 128, BB * HH), 128, AT_SMEM>>>(qkv, ar);
    // 3) output projection (mode 0: plain final output)
    tgemm_tf32<<<dim3(DD / TG_BN, MM / TG_BM), 256, TG_SMEM>>>(
        ar, wot, b_out, out, DD, DD, 0);
}